// round 5
// baseline (speedup 1.0000x reference)
#include <cuda_runtime.h>
#include <cuda_bf16.h>
#include <math.h>
#include <stdint.h>

// Problem constants (fixed by dataset)
#define Bq   2
#define Sq   2048
#define Dq   1024
#define Hq   16
#define DKq  64
#define NR   (Bq*Sq)          // 4096 token rows

// ---------------------------------------------------------------------------
// Scratch (allocation-free rule: __device__ globals)
// ---------------------------------------------------------------------------
__device__ float g_Q [NR*Dq];
__device__ float g_K [NR*Dq];
__device__ __nv_bfloat16 g_xh [NR*Dq];
__device__ __nv_bfloat16 g_xl [NR*Dq];
__device__ __nv_bfloat16 g_aoh[NR*Dq];
__device__ __nv_bfloat16 g_aol[NR*Dq];
__device__ __nv_bfloat16 g_Qh [NR*Dq];
__device__ __nv_bfloat16 g_Ql [NR*Dq];
__device__ __nv_bfloat16 g_Kh [NR*Dq];
__device__ __nv_bfloat16 g_Kl [NR*Dq];
__device__ __nv_bfloat16 g_Vh [NR*Dq];
__device__ __nv_bfloat16 g_Vl [NR*Dq];
__device__ __nv_bfloat16 g_Wh [4*Dq*Dq];   // WQ,WK,WV,WO hi
__device__ __nv_bfloat16 g_Wl [4*Dq*Dq];   // lo
__device__ float g_sin[Sq*32];
__device__ float g_cos[Sq*32];

// ---------------------------------------------------------------------------
// PTX helpers
// ---------------------------------------------------------------------------
__device__ __forceinline__ void mma_bf16(float* d, const uint32_t* a, const uint32_t* b) {
    asm volatile(
        "mma.sync.aligned.m16n8k16.row.col.f32.bf16.bf16.f32 "
        "{%0,%1,%2,%3}, {%4,%5,%6,%7}, {%8,%9}, {%0,%1,%2,%3};\n"
        : "+f"(d[0]), "+f"(d[1]), "+f"(d[2]), "+f"(d[3])
        : "r"(a[0]), "r"(a[1]), "r"(a[2]), "r"(a[3]), "r"(b[0]), "r"(b[1]));
}

__device__ __forceinline__ void ldsm_x4(uint32_t* r, uint32_t addr) {
    asm volatile("ldmatrix.sync.aligned.m8n8.x4.shared.b16 {%0,%1,%2,%3}, [%4];"
        : "=r"(r[0]), "=r"(r[1]), "=r"(r[2]), "=r"(r[3]) : "r"(addr));
}
__device__ __forceinline__ void ldsm_x4_t(uint32_t* r, uint32_t addr) {
    asm volatile("ldmatrix.sync.aligned.m8n8.x4.trans.shared.b16 {%0,%1,%2,%3}, [%4];"
        : "=r"(r[0]), "=r"(r[1]), "=r"(r[2]), "=r"(r[3]) : "r"(addr));
}
__device__ __forceinline__ void ldsm_x2(uint32_t* r, uint32_t addr) {
    asm volatile("ldmatrix.sync.aligned.m8n8.x2.shared.b16 {%0,%1}, [%2];"
        : "=r"(r[0]), "=r"(r[1]) : "r"(addr));
}

__device__ __forceinline__ uint32_t smem_u32(const void* p) {
    uint32_t a;
    asm("{ .reg .u64 t; cvta.to.shared.u64 t, %1; cvt.u32.u64 %0, t; }"
        : "=r"(a) : "l"(p));
    return a;
}

__device__ __forceinline__ uint32_t pack_bf16(float a, float b) {
    __nv_bfloat162 t = __floats2bfloat162_rn(a, b);
    return *reinterpret_cast<uint32_t*>(&t);
}

__device__ __forceinline__ void cp16(uint32_t saddr, const void* gaddr) {
    asm volatile("cp.async.cg.shared.global [%0], [%1], 16;"
        :: "r"(saddr), "l"(gaddr));
}
#define CP_COMMIT() asm volatile("cp.async.commit_group;")
#define CP_WAIT0()  asm volatile("cp.async.wait_group 0;")

// ---------------------------------------------------------------------------
// fp32 -> (bf16 hi, bf16 lo) split with scale. One float4 per thread.
// ---------------------------------------------------------------------------
__global__ void __launch_bounds__(256) split_kernel(const float* __restrict__ X,
                                                    __nv_bfloat16* __restrict__ H,
                                                    __nv_bfloat16* __restrict__ L,
                                                    int n4, float scale)
{
    int i = blockIdx.x * 256 + threadIdx.x;
    if (i >= n4) return;
    float4 v = ((const float4*)X)[i];
    float f[4] = {v.x * scale, v.y * scale, v.z * scale, v.w * scale};
    __nv_bfloat16 h[4], l[4];
#pragma unroll
    for (int j = 0; j < 4; j++) {
        h[j] = __float2bfloat16(f[j]);
        l[j] = __float2bfloat16(f[j] - __bfloat162float(h[j]));
    }
    __nv_bfloat162* H2 = (__nv_bfloat162*)H;
    __nv_bfloat162* L2 = (__nv_bfloat162*)L;
    H2[2*i]   = __nv_bfloat162(h[0], h[1]);
    H2[2*i+1] = __nv_bfloat162(h[2], h[3]);
    L2[2*i]   = __nv_bfloat162(l[0], l[1]);
    L2[2*i+1] = __nv_bfloat162(l[2], l[3]);
}

// ---------------------------------------------------------------------------
// Split-bf16 tensor-core GEMM with 2-stage cp.async pipeline.
// CTA 128x128, 8 warps of 64x32, K-chunk 64, 3 passes (AhBh+AlBh+AhBl).
// EPI: 0 -> fp32 C; 1 -> bf16 hi/lo (CH, CL).
// ---------------------------------------------------------------------------
#define GSTRIDE 72
#define GTILE   (128 * GSTRIDE)
#define GSTAGE_B (4 * GTILE * 2)           // bytes per stage (Ah,Al,Bh,Bl)
#define GEMM_SMEM (2 * GSTAGE_B)

template<int EPI>
__global__ void __launch_bounds__(256) gemm_tc(const __nv_bfloat16* __restrict__ Ah,
                                               const __nv_bfloat16* __restrict__ Al,
                                               const __nv_bfloat16* __restrict__ Bh,
                                               const __nv_bfloat16* __restrict__ Bl,
                                               float* __restrict__ C,
                                               __nv_bfloat16* __restrict__ CH,
                                               __nv_bfloat16* __restrict__ CL,
                                               int M, int N, int K)
{
    extern __shared__ __nv_bfloat16 smg[];

    const int tid  = threadIdx.x;
    const int lane = tid & 31;
    const int wid  = tid >> 5;
    const int bm   = blockIdx.y * 128;
    const int bn   = blockIdx.x * 128;
    const int wm   = (wid >> 2) * 64;
    const int wn   = (wid & 3) * 32;

    const uint32_t sb = smem_u32(smg);

    float acc[4][4][4];
#pragma unroll
    for (int mt = 0; mt < 4; mt++)
#pragma unroll
        for (int nt = 0; nt < 4; nt++)
#pragma unroll
            for (int r = 0; r < 4; r++) acc[mt][nt][r] = 0.f;

    const uint32_t offA = ((lane & 15) * GSTRIDE + (lane >> 4) * 8) * 2;
    const uint32_t offB = ((lane & 7) * GSTRIDE + ((lane >> 3) & 1) * 8) * 2;

    // async tile loader: 4 tiles of 128x64 bf16 into stage
    auto issue = [&](int kt, int stage) {
        const int k0 = kt * 64;
        const uint32_t stb = sb + stage * GSTAGE_B;
#pragma unroll
        for (int j = 0; j < 4; j++) {
            int idx = tid + j * 256;
            int row = idx >> 3;
            int cq  = idx & 7;
            uint32_t so = (uint32_t)(row * GSTRIDE + cq * 8) * 2;
            size_t ga = (size_t)(bm + row) * K + k0 + cq * 8;
            size_t gb = (size_t)(bn + row) * K + k0 + cq * 8;
            cp16(stb                 + so, Ah + ga);
            cp16(stb + GTILE * 2     + so, Al + ga);
            cp16(stb + 2 * GTILE * 2 + so, Bh + gb);
            cp16(stb + 3 * GTILE * 2 + so, Bl + gb);
        }
        CP_COMMIT();
    };

    const int KT = K / 64;
    issue(0, 0);

    for (int kt = 0; kt < KT; kt++) {
        CP_WAIT0();
        __syncthreads();
        if (kt + 1 < KT) issue(kt + 1, (kt + 1) & 1);

        const uint32_t stb = sb + (kt & 1) * GSTAGE_B;
        const uint32_t aAh = stb;
        const uint32_t aAl = stb + GTILE * 2;
        const uint32_t aBh = stb + 2 * GTILE * 2;
        const uint32_t aBl = stb + 3 * GTILE * 2;

#pragma unroll
        for (int ks = 0; ks < 4; ks++) {
            const uint32_t kof = (uint32_t)(ks * 16 * 2);
            uint32_t bh[4][2], bl[4][2], af[4][4];
#pragma unroll
            for (int nt = 0; nt < 4; nt++) {
                uint32_t ro = (uint32_t)((wn + nt * 8) * GSTRIDE * 2) + kof;
                ldsm_x2(bh[nt], aBh + ro + offB);
                ldsm_x2(bl[nt], aBl + ro + offB);
            }
#pragma unroll
            for (int mt = 0; mt < 4; mt++) {
                uint32_t ro = (uint32_t)((wm + mt * 16) * GSTRIDE * 2) + kof;
                ldsm_x4(af[mt], aAh + ro + offA);
            }
#pragma unroll
            for (int mt = 0; mt < 4; mt++)
#pragma unroll
                for (int nt = 0; nt < 4; nt++) {
                    mma_bf16(acc[mt][nt], af[mt], bh[nt]);
                    mma_bf16(acc[mt][nt], af[mt], bl[nt]);
                }
#pragma unroll
            for (int mt = 0; mt < 4; mt++) {
                uint32_t ro = (uint32_t)((wm + mt * 16) * GSTRIDE * 2) + kof;
                ldsm_x4(af[mt], aAl + ro + offA);
            }
#pragma unroll
            for (int mt = 0; mt < 4; mt++)
#pragma unroll
                for (int nt = 0; nt < 4; nt++)
                    mma_bf16(acc[mt][nt], af[mt], bh[nt]);
        }
        __syncthreads();
    }

    const int er = lane >> 2;
    const int ec = (lane & 3) * 2;
#pragma unroll
    for (int mt = 0; mt < 4; mt++) {
        const int row = bm + wm + mt * 16 + er;
#pragma unroll
        for (int nt = 0; nt < 4; nt++) {
            const int col = bn + wn + nt * 8 + ec;
            if (EPI == 0) {
                *(float2*)(C + (size_t)row * N + col) =
                    make_float2(acc[mt][nt][0], acc[mt][nt][1]);
                *(float2*)(C + (size_t)(row + 8) * N + col) =
                    make_float2(acc[mt][nt][2], acc[mt][nt][3]);
            } else {
                float v0 = acc[mt][nt][0], v1 = acc[mt][nt][1];
                float v2 = acc[mt][nt][2], v3 = acc[mt][nt][3];
                float h0 = __bfloat162float(__float2bfloat16(v0));
                float h1 = __bfloat162float(__float2bfloat16(v1));
                float h2 = __bfloat162float(__float2bfloat16(v2));
                float h3 = __bfloat162float(__float2bfloat16(v3));
                *(uint32_t*)(CH + (size_t)row * N + col)       = pack_bf16(h0, h1);
                *(uint32_t*)(CL + (size_t)row * N + col)       = pack_bf16(v0 - h0, v1 - h1);
                *(uint32_t*)(CH + (size_t)(row + 8) * N + col) = pack_bf16(h2, h3);
                *(uint32_t*)(CL + (size_t)(row + 8) * N + col) = pack_bf16(v2 - h2, v3 - h3);
            }
        }
    }
}

// ---------------------------------------------------------------------------
// RoPE table: sin/cos[s][p] for s<2048, p<32.
// ---------------------------------------------------------------------------
__global__ void __launch_bounds__(256) rope_table_kernel(float* __restrict__ st,
                                                         float* __restrict__ ct)
{
    int i = blockIdx.x * 256 + threadIdx.x;
    int s = i >> 5, p = i & 31;
    double f = exp(-(double)p * (9.210340371976184 / 32.0));
    float a = (float)((double)s * f);
    float sv, cv;
    sincosf(a, &sv, &cv);
    st[i] = sv;
    ct[i] = cv;
}

// ---------------------------------------------------------------------------
// Fused RMSNorm + RoPE + bf16 hi/lo split (scale folded). fp32 in, hi/lo out.
// ---------------------------------------------------------------------------
__global__ void __launch_bounds__(256) norm_rope_split(const float* __restrict__ T,
                                                       __nv_bfloat16* __restrict__ H,
                                                       __nv_bfloat16* __restrict__ L,
                                                       const float* __restrict__ gain,
                                                       const float* __restrict__ st,
                                                       const float* __restrict__ ct,
                                                       float scale)
{
    const int n = blockIdx.x;
    const int s = n % Sq;
    const float* row = T + (size_t)n * Dq;
    const int t = threadIdx.x;

    float4 x = ((const float4*)row)[t];
    float ss = x.x * x.x + x.y * x.y + x.z * x.z + x.w * x.w;
#pragma unroll
    for (int o = 16; o > 0; o >>= 1) ss += __shfl_xor_sync(0xffffffffu, ss, o);

    __shared__ float wsum[8];
    if ((t & 31) == 0) wsum[t >> 5] = ss;
    __syncthreads();
    float tot = 0.f;
#pragma unroll
    for (int i = 0; i < 8; i++) tot += wsum[i];

    const float rinv = rsqrtf(tot * (1.0f / 1024.0f) + 1e-5f) ;
    const float4 g = ((const float4*)gain)[t];

    const int p0 = ((t * 4) & 63) >> 1;
    const float s0 = st[s * 32 + p0],     c0 = ct[s * 32 + p0];
    const float s1 = st[s * 32 + p0 + 1], c1 = ct[s * 32 + p0 + 1];

    const float e0 = x.x * rinv * g.x, o0 = x.y * rinv * g.y;
    const float e1 = x.z * rinv * g.z, o1 = x.w * rinv * g.w;

    float r0 = (e0 * c0 - o0 * s0) * scale;
    float r1 = (o0 * c0 + e0 * s0) * scale;
    float r2 = (e1 * c1 - o1 * s1) * scale;
    float r3 = (o1 * c1 + e1 * s1) * scale;

    float h0 = __bfloat162float(__float2bfloat16(r0));
    float h1 = __bfloat162float(__float2bfloat16(r1));
    float h2 = __bfloat162float(__float2bfloat16(r2));
    float h3 = __bfloat162float(__float2bfloat16(r3));

    uint32_t* H32 = (uint32_t*)(H + (size_t)n * Dq);
    uint32_t* L32 = (uint32_t*)(L + (size_t)n * Dq);
    H32[2*t]   = pack_bf16(h0, h1);
    H32[2*t+1] = pack_bf16(h2, h3);
    L32[2*t]   = pack_bf16(r0 - h0, r1 - h1);
    L32[2*t+1] = pack_bf16(r2 - h2, r3 - h3);
}

// ---------------------------------------------------------------------------
// Tensor-core causal flash attention, 128-query CTAs, 8 warps,
// 2-stage cp.async K/V pipeline. 3-pass split-bf16 QK^T and PV.
// ---------------------------------------------------------------------------
#define FSTR 72
#define FQT  (128 * FSTR)                  // Q tile halfwords
#define FKT  (64 * FSTR)                   // K/V tile halfwords
#define FSTAGE_B (4 * FKT * 2)             // bytes per K/V stage
#define FLASH_SMEM (2 * FQT * 2 + 2 * FSTAGE_B)

__global__ void __launch_bounds__(256) flash_tc(
    const __nv_bfloat16* __restrict__ Qh, const __nv_bfloat16* __restrict__ Ql,
    const __nv_bfloat16* __restrict__ Kh, const __nv_bfloat16* __restrict__ Kl,
    const __nv_bfloat16* __restrict__ Vh, const __nv_bfloat16* __restrict__ Vl,
    __nv_bfloat16* __restrict__ AOh, __nv_bfloat16* __restrict__ AOl)
{
    extern __shared__ __nv_bfloat16 smf[];

    const int tid  = threadIdx.x;
    const int lane = tid & 31;
    const int warp = tid >> 5;
    const int q0 = blockIdx.x * 128;
    const int h  = blockIdx.y;
    const int b  = blockIdx.z;

    const uint32_t sb   = smem_u32(smf);
    const uint32_t aQh  = sb;
    const uint32_t aQl  = sb + FQT * 2;
    const uint32_t kvsb = sb + 2 * FQT * 2;   // stage 0 base

    // ---- load Q tile (128 rows x 64 dims, hi/lo) ----
    {
        const size_t gbase = ((size_t)b * Sq + q0) * Dq + h * DKq;
        __nv_bfloat16* sQh = smf;
        __nv_bfloat16* sQl = smf + FQT;
#pragma unroll
        for (int j = 0; j < 4; j++) {
            int idx = tid + j * 256;          // 0..1023
            int row = idx >> 3;
            int cq  = idx & 7;
            size_t g = gbase + (size_t)row * Dq + cq * 8;
            uint32_t so = (uint32_t)(row * FSTR + cq * 8);
            *(uint4*)(sQh + so) = *(const uint4*)(Qh + g);
            *(uint4*)(sQl + so) = *(const uint4*)(Ql + g);
        }
    }

    const size_t kvbase = ((size_t)b * Sq) * Dq + h * DKq;
    auto issue_kv = [&](int t, int stage) {
        const int k0 = t * 64;
        const uint32_t stb = kvsb + stage * FSTAGE_B;
#pragma unroll
        for (int j = 0; j < 2; j++) {
            int idx = tid + j * 256;          // 0..511
            int row = idx >> 3;
            int cq  = idx & 7;
            size_t g = kvbase + (size_t)(k0 + row) * Dq + cq * 8;
            uint32_t so = (uint32_t)(row * FSTR + cq * 8) * 2;
            cp16(stb               + so, Kh + g);
            cp16(stb + FKT * 2     + so, Kl + g);
            cp16(stb + 2 * FKT * 2 + so, Vh + g);
            cp16(stb + 3 * FKT * 2 + so, Vl + g);
        }
        CP_COMMIT();
    };

    issue_kv(0, 0);
    __syncthreads();

    // ---- Q A-fragments (4 k-chunks, hi/lo) ----
    uint32_t qa_h[4][4], qa_l[4][4];
    const uint32_t offA = (uint32_t)(((lane & 15) * FSTR + (lane >> 4) * 8) * 2);
    const uint32_t qwb  = (uint32_t)(warp * 16 * FSTR * 2);
#pragma unroll
    for (int kc = 0; kc < 4; kc++) {
        ldsm_x4(qa_h[kc], aQh + qwb + (uint32_t)(kc * 32) + offA);
        ldsm_x4(qa_l[kc], aQl + qwb + (uint32_t)(kc * 32) + offA);
    }

    float m0 = -1e30f, m1 = -1e30f, l0 = 0.f, l1 = 0.f;
    float oacc[8][4];
#pragma unroll
    for (int nt = 0; nt < 8; nt++)
#pragma unroll
        for (int r = 0; r < 4; r++) oacc[nt][r] = 0.f;

    const int r0g = q0 + warp * 16 + (lane >> 2);

    const int ntiles = 2 * blockIdx.x + 2;
    for (int t = 0; t < ntiles; t++) {
        const int k0 = t * 64;
        CP_WAIT0();
        __syncthreads();
        if (t + 1 < ntiles) issue_kv(t + 1, (t + 1) & 1);

        const uint32_t stb = kvsb + (t & 1) * FSTAGE_B;
        const uint32_t aKh = stb;
        const uint32_t aKl = stb + FKT * 2;
        const uint32_t aVh = stb + 2 * FKT * 2;
        const uint32_t aVl = stb + 3 * FKT * 2;

        // ---- S = Q K^T ----
        float sacc[8][4];
#pragma unroll
        for (int nt = 0; nt < 8; nt++)
#pragma unroll
            for (int r = 0; r < 4; r++) sacc[nt][r] = 0.f;

#pragma unroll
        for (int nt = 0; nt < 8; nt++) {
            uint32_t kbh[8], kbl[8];
            uint32_t rb = (uint32_t)(((nt * 8 + (lane & 7)) * FSTR + (lane >> 3) * 8) * 2);
            ldsm_x4(kbh,     aKh + rb);
            ldsm_x4(kbh + 4, aKh + rb + 64);
            ldsm_x4(kbl,     aKl + rb);
            ldsm_x4(kbl + 4, aKl + rb + 64);
#pragma unroll
            for (int kc = 0; kc < 4; kc++) {
                mma_bf16(sacc[nt], qa_h[kc], kbh + kc * 2);
                mma_bf16(sacc[nt], qa_l[kc], kbh + kc * 2);
                mma_bf16(sacc[nt], qa_h[kc], kbl + kc * 2);
            }
        }

        // ---- causal mask (only warps whose rows intersect this tile) ----
        if (k0 + 63 > r0g) {
            const int cb = k0 + 2 * (lane & 3);
#pragma unroll
            for (int nt = 0; nt < 8; nt++) {
                int c = cb + nt * 8;
                if (c     > r0g)     sacc[nt][0] = -1e30f;
                if (c + 1 > r0g)     sacc[nt][1] = -1e30f;
                if (c     > r0g + 8) sacc[nt][2] = -1e30f;
                if (c + 1 > r0g + 8) sacc[nt][3] = -1e30f;
            }
        }

        // ---- online softmax ----
        float mx0 = -1e30f, mx1 = -1e30f;
#pragma unroll
        for (int nt = 0; nt < 8; nt++) {
            mx0 = fmaxf(mx0, fmaxf(sacc[nt][0], sacc[nt][1]));
            mx1 = fmaxf(mx1, fmaxf(sacc[nt][2], sacc[nt][3]));
        }
        mx0 = fmaxf(mx0, __shfl_xor_sync(0xffffffffu, mx0, 1));
        mx0 = fmaxf(mx0, __shfl_xor_sync(0xffffffffu, mx0, 2));
        mx1 = fmaxf(mx1, __shfl_xor_sync(0xffffffffu, mx1, 1));
        mx1 = fmaxf(mx1, __shfl_xor_sync(0xffffffffu, mx1, 2));

        const float m0n = fmaxf(m0, mx0);
        const float m1n = fmaxf(m1, mx1);
        const float a0 = __expf(m0 - m0n);
        const float a1 = __expf(m1 - m1n);

        float rs0 = 0.f, rs1 = 0.f;
#pragma unroll
        for (int nt = 0; nt < 8; nt++) {
            float p0 = __expf(sacc[nt][0] - m0n);
            float p1 = __expf(sacc[nt][1] - m0n);
            float p2 = __expf(sacc[nt][2] - m1n);
            float p3 = __expf(sacc[nt][3] - m1n);
            sacc[nt][0] = p0; sacc[nt][1] = p1; sacc[nt][2] = p2; sacc[nt][3] = p3;
            rs0 += p0 + p1;
            rs1 += p2 + p3;
        }
        rs0 += __shfl_xor_sync(0xffffffffu, rs0, 1);
        rs0 += __shfl_xor_sync(0xffffffffu, rs0, 2);
        rs1 += __shfl_xor_sync(0xffffffffu, rs1, 1);
        rs1 += __shfl_xor_sync(0xffffffffu, rs1, 2);

        l0 = l0 * a0 + rs0;
        l1 = l1 * a1 + rs1;
        m0 = m0n;
        m1 = m1n;
#pragma unroll
        for (int nt = 0; nt < 8; nt++) {
            oacc[nt][0] *= a0; oacc[nt][1] *= a0;
            oacc[nt][2] *= a1; oacc[nt][3] *= a1;
        }

        // ---- P -> A-fragments (hi/lo) ----
        uint32_t pa_h[4][4], pa_l[4][4];
#pragma unroll
        for (int kc = 0; kc < 4; kc++) {
#pragma unroll
            for (int half = 0; half < 2; half++) {
                const float* v = sacc[2 * kc + half];
                float h00 = __bfloat162float(__float2bfloat16(v[0]));
                float h01 = __bfloat162float(__float2bfloat16(v[1]));
                float h10 = __bfloat162float(__float2bfloat16(v[2]));
                float h11 = __bfloat162float(__float2bfloat16(v[3]));
                pa_h[kc][0 + 2 * half] = pack_bf16(h00, h01);
                pa_h[kc][1 + 2 * half] = pack_bf16(h10, h11);
                pa_l[kc][0 + 2 * half] = pack_bf16(v[0] - h00, v[1] - h01);
                pa_l[kc][1 + 2 * half] = pack_bf16(v[2] - h10, v[3] - h11);
            }
        }

        // ---- O += P V ----
#pragma unroll
        for (int np = 0; np < 4; np++) {
#pragma unroll
            for (int kc = 0; kc < 4; kc++) {
                uint32_t vbh[4], vbl[4];
                int g = lane >> 3;
                int key = kc * 16 + (g & 1) * 8 + (lane & 7);
                int dim = np * 16 + (g >> 1) * 8;
                uint32_t ad = (uint32_t)((key * FSTR + dim) * 2);
                ldsm_x4_t(vbh, aVh + ad);
                ldsm_x4_t(vbl, aVl + ad);
                mma_bf16(oacc[2 * np],     pa_h[kc], vbh);
                mma_bf16(oacc[2 * np],     pa_l[kc], vbh);
                mma_bf16(oacc[2 * np],     pa_h[kc], vbl);
                mma_bf16(oacc[2 * np + 1], pa_h[kc], vbh + 2);
                mma_bf16(oacc[2 * np + 1], pa_l[kc], vbh + 2);
                mma_bf16(oacc[2 * np + 1], pa_h[kc], vbl + 2);
            }
        }
        __syncthreads();
    }

    // ---- finalize & store as bf16 hi/lo ----
    const float i0 = 1.f / l0;
    const float i1 = 1.f / l1;
    const size_t ob0 = ((size_t)b * Sq + r0g) * Dq + h * DKq + 2 * (lane & 3);
#pragma unroll
    for (int nt = 0; nt < 8; nt++) {
        float x0 = oacc[nt][0] * i0, x1 = oacc[nt][1] * i0;
        float y0 = oacc[nt][2] * i1, y1 = oacc[nt][3] * i1;
        float hx0 = __bfloat162float(__float2bfloat16(x0));
        float hx1 = __bfloat162float(__float2bfloat16(x1));
        float hy0 = __bfloat162float(__float2bfloat16(y0));
        float hy1 = __bfloat162float(__float2bfloat16(y1));
        size_t o0 = ob0 + nt * 8;
        size_t o1 = o0 + 8 * (size_t)Dq;
        *(uint32_t*)(AOh + o0) = pack_bf16(hx0, hx1);
        *(uint32_t*)(AOl + o0) = pack_bf16(x0 - hx0, x1 - hx1);
        *(uint32_t*)(AOh + o1) = pack_bf16(hy0, hy1);
        *(uint32_t*)(AOl + o1) = pack_bf16(y0 - hy0, y1 - hy1);
    }
}

// ---------------------------------------------------------------------------
extern "C" void kernel_launch(void* const* d_in, const int* in_sizes, int n_in,
                              void* d_out, int out_size)
{
    const float* x    = (const float*)d_in[0];
    const float* W_Q  = (const float*)d_in[1];
    const float* W_K  = (const float*)d_in[2];
    const float* W_V  = (const float*)d_in[3];
    const float* W_O  = (const float*)d_in[4];
    const float* gain = (const float*)d_in[5];
    float* out = (float*)d_out;

    float *Qp, *Kp, *sinp, *cosp;
    __nv_bfloat16 *xh, *xl, *aoh, *aol, *Wh, *Wl;
    __nv_bfloat16 *qh, *ql, *kh, *kl, *vh, *vl;
    cudaGetSymbolAddress((void**)&Qp,   g_Q);
    cudaGetSymbolAddress((void**)&Kp,   g_K);
    cudaGetSymbolAddress((void**)&sinp, g_sin);
    cudaGetSymbolAddress((void**)&cosp, g_cos);
    cudaGetSymbolAddress((void**)&xh,   g_xh);
    cudaGetSymbolAddress((void**)&xl,   g_xl);
    cudaGetSymbolAddress((void**)&aoh,  g_aoh);
    cudaGetSymbolAddress((void**)&aol,  g_aol);
    cudaGetSymbolAddress((void**)&Wh,   g_Wh);
    cudaGetSymbolAddress((void**)&Wl,   g_Wl);
    cudaGetSymbolAddress((void**)&qh,   g_Qh);
    cudaGetSymbolAddress((void**)&ql,   g_Ql);
    cudaGetSymbolAddress((void**)&kh,   g_Kh);
    cudaGetSymbolAddress((void**)&kl,   g_Kl);
    cudaGetSymbolAddress((void**)&vh,   g_Vh);
    cudaGetSymbolAddress((void**)&vl,   g_Vl);

    cudaFuncSetAttribute(gemm_tc<0>,
                         cudaFuncAttributeMaxDynamicSharedMemorySize, GEMM_SMEM);
    cudaFuncSetAttribute(gemm_tc<1>,
                         cudaFuncAttributeMaxDynamicSharedMemorySize, GEMM_SMEM);
    cudaFuncSetAttribute(flash_tc,
                         cudaFuncAttributeMaxDynamicSharedMemorySize, FLASH_SMEM);

    const int nx4 = NR * Dq / 4;
    const int nw4 = Dq * Dq / 4;
    const size_t WSZ = (size_t)Dq * Dq;

    // splits + table
    split_kernel<<<nx4 / 256, 256>>>(x, xh, xl, nx4, 1.f);
    split_kernel<<<nw4 / 256, 256>>>(W_Q, Wh + 0*WSZ, Wl + 0*WSZ, nw4, 1.f);
    split_kernel<<<nw4 / 256, 256>>>(W_K, Wh + 1*WSZ, Wl + 1*WSZ, nw4, 1.f);
    split_kernel<<<nw4 / 256, 256>>>(W_V, Wh + 2*WSZ, Wl + 2*WSZ, nw4, 1.f);
    split_kernel<<<nw4 / 256, 256>>>(W_O, Wh + 3*WSZ, Wl + 3*WSZ, nw4, 1.f);
    rope_table_kernel<<<Sq * 32 / 256, 256>>>(sinp, cosp);

    // projections (Q,K fp32 out; V splits directly to hi/lo)
    dim3 gg(Dq / 128, NR / 128);
    gemm_tc<0><<<gg, 256, GEMM_SMEM>>>(xh, xl, Wh + 0*WSZ, Wl + 0*WSZ, Qp, nullptr, nullptr, NR, Dq, Dq);
    gemm_tc<0><<<gg, 256, GEMM_SMEM>>>(xh, xl, Wh + 1*WSZ, Wl + 1*WSZ, Kp, nullptr, nullptr, NR, Dq, Dq);
    gemm_tc<1><<<gg, 256, GEMM_SMEM>>>(xh, xl, Wh + 2*WSZ, Wl + 2*WSZ, nullptr, vh, vl, NR, Dq, Dq);

    // fused norm+rope+split (1/8 folded into Q)
    norm_rope_split<<<NR, 256>>>(Qp, qh, ql, gain, sinp, cosp, 0.125f);
    norm_rope_split<<<NR, 256>>>(Kp, kh, kl, gain, sinp, cosp, 1.f);

    // tensor-core flash attention (128-query CTAs)
    flash_tc<<<dim3(Sq / 128, Hq, Bq), 256, FLASH_SMEM>>>(qh, ql, kh, kl, vh, vl, aoh, aol);

    gemm_tc<0><<<gg, 256, GEMM_SMEM>>>(aoh, aol, Wh + 3*WSZ, Wl + 3*WSZ, out, nullptr, nullptr, NR, Dq, Dq);
}

// round 8
// speedup vs baseline: 1.4040x; 1.4040x over previous
#include <cuda_runtime.h>
#include <cuda_bf16.h>
#include <math.h>
#include <stdint.h>

// Problem constants (fixed by dataset)
#define Bq   2
#define Sq   2048
#define Dq   1024
#define Hq   16
#define DKq  64
#define NR   (Bq*Sq)          // 4096 token rows

// ---------------------------------------------------------------------------
// Scratch (allocation-free rule: __device__ globals)
// ---------------------------------------------------------------------------
__device__ float g_Q [NR*Dq];
__device__ float g_K [NR*Dq];
__device__ __nv_bfloat16 g_xh [NR*Dq];
__device__ __nv_bfloat16 g_xl [NR*Dq];
__device__ __nv_bfloat16 g_aoh[NR*Dq];
__device__ __nv_bfloat16 g_aol[NR*Dq];
__device__ __nv_bfloat16 g_Qh [NR*Dq];
__device__ __nv_bfloat16 g_Ql [NR*Dq];
__device__ __nv_bfloat16 g_Kh [NR*Dq];
__device__ __nv_bfloat16 g_Kl [NR*Dq];
__device__ __nv_bfloat16 g_Vh [NR*Dq];
__device__ __nv_bfloat16 g_Vl [NR*Dq];
__device__ __nv_bfloat16 g_Wh [4*Dq*Dq];   // WQ,WK,WV,WO hi
__device__ __nv_bfloat16 g_Wl [4*Dq*Dq];   // lo
__device__ float g_sin[Sq*32];
__device__ float g_cos[Sq*32];

// ---------------------------------------------------------------------------
// PTX helpers
// ---------------------------------------------------------------------------
__device__ __forceinline__ void mma_bf16(float* d, const uint32_t* a, const uint32_t* b) {
    asm volatile(
        "mma.sync.aligned.m16n8k16.row.col.f32.bf16.bf16.f32 "
        "{%0,%1,%2,%3}, {%4,%5,%6,%7}, {%8,%9}, {%0,%1,%2,%3};\n"
        : "+f"(d[0]), "+f"(d[1]), "+f"(d[2]), "+f"(d[3])
        : "r"(a[0]), "r"(a[1]), "r"(a[2]), "r"(a[3]), "r"(b[0]), "r"(b[1]));
}

__device__ __forceinline__ void ldsm_x4(uint32_t* r, uint32_t addr) {
    asm volatile("ldmatrix.sync.aligned.m8n8.x4.shared.b16 {%0,%1,%2,%3}, [%4];"
        : "=r"(r[0]), "=r"(r[1]), "=r"(r[2]), "=r"(r[3]) : "r"(addr));
}
__device__ __forceinline__ void ldsm_x4_t(uint32_t* r, uint32_t addr) {
    asm volatile("ldmatrix.sync.aligned.m8n8.x4.trans.shared.b16 {%0,%1,%2,%3}, [%4];"
        : "=r"(r[0]), "=r"(r[1]), "=r"(r[2]), "=r"(r[3]) : "r"(addr));
}
__device__ __forceinline__ void ldsm_x2(uint32_t* r, uint32_t addr) {
    asm volatile("ldmatrix.sync.aligned.m8n8.x2.shared.b16 {%0,%1}, [%2];"
        : "=r"(r[0]), "=r"(r[1]) : "r"(addr));
}

__device__ __forceinline__ uint32_t smem_u32(const void* p) {
    uint32_t a;
    asm("{ .reg .u64 t; cvta.to.shared.u64 t, %1; cvt.u32.u64 %0, t; }"
        : "=r"(a) : "l"(p));
    return a;
}

__device__ __forceinline__ uint32_t pack_bf16(float a, float b) {
    __nv_bfloat162 t = __floats2bfloat162_rn(a, b);
    return *reinterpret_cast<uint32_t*>(&t);
}

// ---------------------------------------------------------------------------
// fp32 -> (bf16 hi, bf16 lo) split with scale. One float4 per thread.
// ---------------------------------------------------------------------------
__global__ void __launch_bounds__(256) split_kernel(const float* __restrict__ X,
                                                    __nv_bfloat16* __restrict__ H,
                                                    __nv_bfloat16* __restrict__ L,
                                                    int n4, float scale)
{
    int i = blockIdx.x * 256 + threadIdx.x;
    if (i >= n4) return;
    float4 v = ((const float4*)X)[i];
    float f[4] = {v.x * scale, v.y * scale, v.z * scale, v.w * scale};
    __nv_bfloat16 h[4], l[4];
#pragma unroll
    for (int j = 0; j < 4; j++) {
        h[j] = __float2bfloat16(f[j]);
        l[j] = __float2bfloat16(f[j] - __bfloat162float(h[j]));
    }
    __nv_bfloat162* H2 = (__nv_bfloat162*)H;
    __nv_bfloat162* L2 = (__nv_bfloat162*)L;
    H2[2*i]   = __nv_bfloat162(h[0], h[1]);
    H2[2*i+1] = __nv_bfloat162(h[2], h[3]);
    L2[2*i]   = __nv_bfloat162(l[0], l[1]);
    L2[2*i+1] = __nv_bfloat162(l[2], l[3]);
}

// ---------------------------------------------------------------------------
// Split-bf16 tensor-core GEMM (R4 structure: sync loads, 2 CTAs/SM).
// CTA 128x128, 8 warps of 64x32, K-chunk 64, 3 passes (AhBh+AlBh+AhBl).
// EPI: 0 -> fp32 C; 1 -> bf16 hi/lo (CH, CL).
// ---------------------------------------------------------------------------
#define GSTRIDE 72
#define GTILE   (128 * GSTRIDE)
#define GEMM_SMEM (4 * GTILE * 2)

template<int EPI>
__global__ void __launch_bounds__(256) gemm_tc(const __nv_bfloat16* __restrict__ Ah,
                                               const __nv_bfloat16* __restrict__ Al,
                                               const __nv_bfloat16* __restrict__ Bh,
                                               const __nv_bfloat16* __restrict__ Bl,
                                               float* __restrict__ C,
                                               __nv_bfloat16* __restrict__ CH,
                                               __nv_bfloat16* __restrict__ CL,
                                               int M, int N, int K)
{
    extern __shared__ __nv_bfloat16 smg[];
    __nv_bfloat16* sAh = smg;
    __nv_bfloat16* sAl = smg + GTILE;
    __nv_bfloat16* sBh = smg + 2 * GTILE;
    __nv_bfloat16* sBl = smg + 3 * GTILE;

    const int tid  = threadIdx.x;
    const int lane = tid & 31;
    const int wid  = tid >> 5;
    const int bm   = blockIdx.y * 128;
    const int bn   = blockIdx.x * 128;
    const int wm   = (wid >> 2) * 64;
    const int wn   = (wid & 3) * 32;

    const uint32_t sb = smem_u32(smg);
    const uint32_t aAh = sb;
    const uint32_t aAl = sb + GTILE * 2;
    const uint32_t aBh = sb + 2 * GTILE * 2;
    const uint32_t aBl = sb + 3 * GTILE * 2;

    float acc[4][4][4];
#pragma unroll
    for (int mt = 0; mt < 4; mt++)
#pragma unroll
        for (int nt = 0; nt < 4; nt++)
#pragma unroll
            for (int r = 0; r < 4; r++) acc[mt][nt][r] = 0.f;

    const uint32_t offA = ((lane & 15) * GSTRIDE + (lane >> 4) * 8) * 2;
    const uint32_t offB = ((lane & 7) * GSTRIDE + ((lane >> 3) & 1) * 8) * 2;

    const int KT = K / 64;
    for (int kt = 0; kt < KT; kt++) {
        const int k0 = kt * 64;
        __syncthreads();
#pragma unroll
        for (int j = 0; j < 4; j++) {
            int idx = tid + j * 256;
            int row = idx >> 3;
            int cq  = idx & 7;
            uint32_t so = (uint32_t)(row * GSTRIDE + cq * 8);
            size_t ga = (size_t)(bm + row) * K + k0 + cq * 8;
            size_t gb = (size_t)(bn + row) * K + k0 + cq * 8;
            *(uint4*)(sAh + so) = *(const uint4*)(Ah + ga);
            *(uint4*)(sAl + so) = *(const uint4*)(Al + ga);
            *(uint4*)(sBh + so) = *(const uint4*)(Bh + gb);
            *(uint4*)(sBl + so) = *(const uint4*)(Bl + gb);
        }
        __syncthreads();

#pragma unroll
        for (int ks = 0; ks < 4; ks++) {
            const uint32_t kof = (uint32_t)(ks * 16 * 2);
            uint32_t bh[4][2], bl[4][2], af[4][4];
#pragma unroll
            for (int nt = 0; nt < 4; nt++) {
                uint32_t ro = (uint32_t)((wn + nt * 8) * GSTRIDE * 2) + kof;
                ldsm_x2(bh[nt], aBh + ro + offB);
                ldsm_x2(bl[nt], aBl + ro + offB);
            }
#pragma unroll
            for (int mt = 0; mt < 4; mt++) {
                uint32_t ro = (uint32_t)((wm + mt * 16) * GSTRIDE * 2) + kof;
                ldsm_x4(af[mt], aAh + ro + offA);
            }
#pragma unroll
            for (int mt = 0; mt < 4; mt++)
#pragma unroll
                for (int nt = 0; nt < 4; nt++) {
                    mma_bf16(acc[mt][nt], af[mt], bh[nt]);
                    mma_bf16(acc[mt][nt], af[mt], bl[nt]);
                }
#pragma unroll
            for (int mt = 0; mt < 4; mt++) {
                uint32_t ro = (uint32_t)((wm + mt * 16) * GSTRIDE * 2) + kof;
                ldsm_x4(af[mt], aAl + ro + offA);
            }
#pragma unroll
            for (int mt = 0; mt < 4; mt++)
#pragma unroll
                for (int nt = 0; nt < 4; nt++)
                    mma_bf16(acc[mt][nt], af[mt], bh[nt]);
        }
    }

    const int er = lane >> 2;
    const int ec = (lane & 3) * 2;
#pragma unroll
    for (int mt = 0; mt < 4; mt++) {
        const int row = bm + wm + mt * 16 + er;
#pragma unroll
        for (int nt = 0; nt < 4; nt++) {
            const int col = bn + wn + nt * 8 + ec;
            if (EPI == 0) {
                *(float2*)(C + (size_t)row * N + col) =
                    make_float2(acc[mt][nt][0], acc[mt][nt][1]);
                *(float2*)(C + (size_t)(row + 8) * N + col) =
                    make_float2(acc[mt][nt][2], acc[mt][nt][3]);
            } else {
                float v0 = acc[mt][nt][0], v1 = acc[mt][nt][1];
                float v2 = acc[mt][nt][2], v3 = acc[mt][nt][3];
                float h0 = __bfloat162float(__float2bfloat16(v0));
                float h1 = __bfloat162float(__float2bfloat16(v1));
                float h2 = __bfloat162float(__float2bfloat16(v2));
                float h3 = __bfloat162float(__float2bfloat16(v3));
                *(uint32_t*)(CH + (size_t)row * N + col)       = pack_bf16(h0, h1);
                *(uint32_t*)(CL + (size_t)row * N + col)       = pack_bf16(v0 - h0, v1 - h1);
                *(uint32_t*)(CH + (size_t)(row + 8) * N + col) = pack_bf16(h2, h3);
                *(uint32_t*)(CL + (size_t)(row + 8) * N + col) = pack_bf16(v2 - h2, v3 - h3);
            }
        }
    }
}

// ---------------------------------------------------------------------------
// RoPE table: sin/cos[s][p] for s<2048, p<32.
// ---------------------------------------------------------------------------
__global__ void __launch_bounds__(256) rope_table_kernel(float* __restrict__ st,
                                                         float* __restrict__ ct)
{
    int i = blockIdx.x * 256 + threadIdx.x;
    int s = i >> 5, p = i & 31;
    double f = exp(-(double)p * (9.210340371976184 / 32.0));
    float a = (float)((double)s * f);
    float sv, cv;
    sincosf(a, &sv, &cv);
    st[i] = sv;
    ct[i] = cv;
}

// ---------------------------------------------------------------------------
// Fused RMSNorm + RoPE + bf16 hi/lo split (scale folded). fp32 in, hi/lo out.
// ---------------------------------------------------------------------------
__global__ void __launch_bounds__(256) norm_rope_split(const float* __restrict__ T,
                                                       __nv_bfloat16* __restrict__ H,
                                                       __nv_bfloat16* __restrict__ L,
                                                       const float* __restrict__ gain,
                                                       const float* __restrict__ st,
                                                       const float* __restrict__ ct,
                                                       float scale)
{
    const int n = blockIdx.x;
    const int s = n % Sq;
    const float* row = T + (size_t)n * Dq;
    const int t = threadIdx.x;

    float4 x = ((const float4*)row)[t];
    float ss = x.x * x.x + x.y * x.y + x.z * x.z + x.w * x.w;
#pragma unroll
    for (int o = 16; o > 0; o >>= 1) ss += __shfl_xor_sync(0xffffffffu, ss, o);

    __shared__ float wsum[8];
    if ((t & 31) == 0) wsum[t >> 5] = ss;
    __syncthreads();
    float tot = 0.f;
#pragma unroll
    for (int i = 0; i < 8; i++) tot += wsum[i];

    const float rinv = rsqrtf(tot * (1.0f / 1024.0f) + 1e-5f);
    const float4 g = ((const float4*)gain)[t];

    const int p0 = ((t * 4) & 63) >> 1;
    const float s0 = st[s * 32 + p0],     c0 = ct[s * 32 + p0];
    const float s1 = st[s * 32 + p0 + 1], c1 = ct[s * 32 + p0 + 1];

    const float e0 = x.x * rinv * g.x, o0 = x.y * rinv * g.y;
    const float e1 = x.z * rinv * g.z, o1 = x.w * rinv * g.w;

    float r0 = (e0 * c0 - o0 * s0) * scale;
    float r1 = (o0 * c0 + e0 * s0) * scale;
    float r2 = (e1 * c1 - o1 * s1) * scale;
    float r3 = (o1 * c1 + e1 * s1) * scale;

    float h0 = __bfloat162float(__float2bfloat16(r0));
    float h1 = __bfloat162float(__float2bfloat16(r1));
    float h2 = __bfloat162float(__float2bfloat16(r2));
    float h3 = __bfloat162float(__float2bfloat16(r3));

    uint32_t* H32 = (uint32_t*)(H + (size_t)n * Dq);
    uint32_t* L32 = (uint32_t*)(L + (size_t)n * Dq);
    H32[2*t]   = pack_bf16(h0, h1);
    H32[2*t+1] = pack_bf16(h2, h3);
    L32[2*t]   = pack_bf16(r0 - h0, r1 - h1);
    L32[2*t+1] = pack_bf16(r2 - h2, r3 - h3);
}

// ---------------------------------------------------------------------------
// Tensor-core causal flash attention (R4 structure: 64-query CTAs, 4 warps,
// sync smem loads, 4 CTAs/SM). 3-pass split-bf16 QK^T and PV.
// ---------------------------------------------------------------------------
#define FSTR 72
#define FTILE (64 * FSTR)                 // halfwords per 64x64 tile
#define FLASH_SMEM (6 * FTILE * 2)        // Qh,Ql,Kh,Kl,Vh,Vl

__global__ void __launch_bounds__(128) flash_tc(
    const __nv_bfloat16* __restrict__ Qh, const __nv_bfloat16* __restrict__ Ql,
    const __nv_bfloat16* __restrict__ Kh, const __nv_bfloat16* __restrict__ Kl,
    const __nv_bfloat16* __restrict__ Vh, const __nv_bfloat16* __restrict__ Vl,
    __nv_bfloat16* __restrict__ AOh, __nv_bfloat16* __restrict__ AOl)
{
    extern __shared__ __nv_bfloat16 smf[];
    __nv_bfloat16* sQh = smf;
    __nv_bfloat16* sQl = smf + FTILE;
    __nv_bfloat16* sKh = smf + 2 * FTILE;
    __nv_bfloat16* sKl = smf + 3 * FTILE;
    __nv_bfloat16* sVh = smf + 4 * FTILE;
    __nv_bfloat16* sVl = smf + 5 * FTILE;

    const int tid  = threadIdx.x;
    const int lane = tid & 31;
    const int warp = tid >> 5;
    const int q0 = blockIdx.x * 64;
    const int h  = blockIdx.y;
    const int b  = blockIdx.z;

    const uint32_t sb  = smem_u32(smf);
    const uint32_t aQh = sb;
    const uint32_t aQl = sb +     FTILE * 2;
    const uint32_t aKh = sb + 2 * FTILE * 2;
    const uint32_t aKl = sb + 3 * FTILE * 2;
    const uint32_t aVh = sb + 4 * FTILE * 2;
    const uint32_t aVl = sb + 5 * FTILE * 2;

    // ---- load Q tile (64 rows x 64 dims) ----
    {
        const size_t gbase = ((size_t)b * Sq + q0) * Dq + h * DKq;
#pragma unroll
        for (int j = 0; j < 4; j++) {
            int idx = tid + j * 128;          // 0..511
            int row = idx >> 3;
            int cq  = idx & 7;
            size_t g = gbase + (size_t)row * Dq + cq * 8;
            uint32_t so = (uint32_t)(row * FSTR + cq * 8);
            *(uint4*)(sQh + so) = *(const uint4*)(Qh + g);
            *(uint4*)(sQl + so) = *(const uint4*)(Ql + g);
        }
    }
    __syncthreads();

    // ---- Q A-fragments (4 k-chunks) ----
    uint32_t qa_h[4][4], qa_l[4][4];
    const uint32_t offA = (uint32_t)(((lane & 15) * FSTR + (lane >> 4) * 8) * 2);
    const uint32_t qwb  = (uint32_t)(warp * 16 * FSTR * 2);
#pragma unroll
    for (int kc = 0; kc < 4; kc++) {
        ldsm_x4(qa_h[kc], aQh + qwb + (uint32_t)(kc * 32) + offA);
        ldsm_x4(qa_l[kc], aQl + qwb + (uint32_t)(kc * 32) + offA);
    }

    float m0 = -1e30f, m1 = -1e30f, l0 = 0.f, l1 = 0.f;
    float oacc[8][4];
#pragma unroll
    for (int nt = 0; nt < 8; nt++)
#pragma unroll
        for (int r = 0; r < 4; r++) oacc[nt][r] = 0.f;

    const int r0g = q0 + warp * 16 + (lane >> 2);

    const int ntiles = blockIdx.x + 1;
    for (int t = 0; t < ntiles; t++) {
        const int k0 = t * 64;
        __syncthreads();
        {
            const size_t kb = ((size_t)b * Sq + k0) * Dq + h * DKq;
#pragma unroll
            for (int j = 0; j < 4; j++) {
                int idx = tid + j * 128;
                int row = idx >> 3;
                int cq  = idx & 7;
                size_t g = kb + (size_t)row * Dq + cq * 8;
                uint32_t so = (uint32_t)(row * FSTR + cq * 8);
                *(uint4*)(sKh + so) = *(const uint4*)(Kh + g);
                *(uint4*)(sKl + so) = *(const uint4*)(Kl + g);
                *(uint4*)(sVh + so) = *(const uint4*)(Vh + g);
                *(uint4*)(sVl + so) = *(const uint4*)(Vl + g);
            }
        }
        __syncthreads();

        // ---- S = Q K^T ----
        float sacc[8][4];
#pragma unroll
        for (int nt = 0; nt < 8; nt++)
#pragma unroll
            for (int r = 0; r < 4; r++) sacc[nt][r] = 0.f;

#pragma unroll
        for (int nt = 0; nt < 8; nt++) {
            uint32_t kbh[8], kbl[8];
            uint32_t rb = (uint32_t)(((nt * 8 + (lane & 7)) * FSTR + (lane >> 3) * 8) * 2);
            ldsm_x4(kbh,     aKh + rb);
            ldsm_x4(kbh + 4, aKh + rb + 64);
            ldsm_x4(kbl,     aKl + rb);
            ldsm_x4(kbl + 4, aKl + rb + 64);
#pragma unroll
            for (int kc = 0; kc < 4; kc++) {
                mma_bf16(sacc[nt], qa_h[kc], kbh + kc * 2);
                mma_bf16(sacc[nt], qa_l[kc], kbh + kc * 2);
                mma_bf16(sacc[nt], qa_h[kc], kbl + kc * 2);
            }
        }

        // ---- causal mask (diagonal tile only) ----
        if (t == blockIdx.x) {
            const int cb = k0 + 2 * (lane & 3);
#pragma unroll
            for (int nt = 0; nt < 8; nt++) {
                int c = cb + nt * 8;
                if (c     > r0g)     sacc[nt][0] = -1e30f;
                if (c + 1 > r0g)     sacc[nt][1] = -1e30f;
                if (c     > r0g + 8) sacc[nt][2] = -1e30f;
                if (c + 1 > r0g + 8) sacc[nt][3] = -1e30f;
            }
        }

        // ---- online softmax ----
        float mx0 = -1e30f, mx1 = -1e30f;
#pragma unroll
        for (int nt = 0; nt < 8; nt++) {
            mx0 = fmaxf(mx0, fmaxf(sacc[nt][0], sacc[nt][1]));
            mx1 = fmaxf(mx1, fmaxf(sacc[nt][2], sacc[nt][3]));
        }
        mx0 = fmaxf(mx0, __shfl_xor_sync(0xffffffffu, mx0, 1));
        mx0 = fmaxf(mx0, __shfl_xor_sync(0xffffffffu, mx0, 2));
        mx1 = fmaxf(mx1, __shfl_xor_sync(0xffffffffu, mx1, 1));
        mx1 = fmaxf(mx1, __shfl_xor_sync(0xffffffffu, mx1, 2));

        const float m0n = fmaxf(m0, mx0);
        const float m1n = fmaxf(m1, mx1);
        const float a0 = __expf(m0 - m0n);
        const float a1 = __expf(m1 - m1n);

        float rs0 = 0.f, rs1 = 0.f;
#pragma unroll
        for (int nt = 0; nt < 8; nt++) {
            float p0 = __expf(sacc[nt][0] - m0n);
            float p1 = __expf(sacc[nt][1] - m0n);
            float p2 = __expf(sacc[nt][2] - m1n);
            float p3 = __expf(sacc[nt][3] - m1n);
            sacc[nt][0] = p0; sacc[nt][1] = p1; sacc[nt][2] = p2; sacc[nt][3] = p3;
            rs0 += p0 + p1;
            rs1 += p2 + p3;
        }
        rs0 += __shfl_xor_sync(0xffffffffu, rs0, 1);
        rs0 += __shfl_xor_sync(0xffffffffu, rs0, 2);
        rs1 += __shfl_xor_sync(0xffffffffu, rs1, 1);
        rs1 += __shfl_xor_sync(0xffffffffu, rs1, 2);

        l0 = l0 * a0 + rs0;
        l1 = l1 * a1 + rs1;
        m0 = m0n;
        m1 = m1n;
#pragma unroll
        for (int nt = 0; nt < 8; nt++) {
            oacc[nt][0] *= a0; oacc[nt][1] *= a0;
            oacc[nt][2] *= a1; oacc[nt][3] *= a1;
        }

        // ---- P -> A-fragments (hi/lo) ----
        uint32_t pa_h[4][4], pa_l[4][4];
#pragma unroll
        for (int kc = 0; kc < 4; kc++) {
#pragma unroll
            for (int half = 0; half < 2; half++) {
                const float* v = sacc[2 * kc + half];
                float h00 = __bfloat162float(__float2bfloat16(v[0]));
                float h01 = __bfloat162float(__float2bfloat16(v[1]));
                float h10 = __bfloat162float(__float2bfloat16(v[2]));
                float h11 = __bfloat162float(__float2bfloat16(v[3]));
                pa_h[kc][0 + 2 * half] = pack_bf16(h00, h01);
                pa_h[kc][1 + 2 * half] = pack_bf16(h10, h11);
                pa_l[kc][0 + 2 * half] = pack_bf16(v[0] - h00, v[1] - h01);
                pa_l[kc][1 + 2 * half] = pack_bf16(v[2] - h10, v[3] - h11);
            }
        }

        // ---- O += P V ----
#pragma unroll
        for (int np = 0; np < 4; np++) {
#pragma unroll
            for (int kc = 0; kc < 4; kc++) {
                uint32_t vbh[4], vbl[4];
                int g = lane >> 3;
                int key = kc * 16 + (g & 1) * 8 + (lane & 7);
                int dim = np * 16 + (g >> 1) * 8;
                uint32_t ad = (uint32_t)((key * FSTR + dim) * 2);
                ldsm_x4_t(vbh, aVh + ad);
                ldsm_x4_t(vbl, aVl + ad);
                mma_bf16(oacc[2 * np],     pa_h[kc], vbh);
                mma_bf16(oacc[2 * np],     pa_l[kc], vbh);
                mma_bf16(oacc[2 * np],     pa_h[kc], vbl);
                mma_bf16(oacc[2 * np + 1], pa_h[kc], vbh + 2);
                mma_bf16(oacc[2 * np + 1], pa_l[kc], vbh + 2);
                mma_bf16(oacc[2 * np + 1], pa_h[kc], vbl + 2);
            }
        }
    }

    // ---- finalize & store as bf16 hi/lo ----
    const float i0 = 1.f / l0;
    const float i1 = 1.f / l1;
    const size_t ob0 = ((size_t)b * Sq + r0g) * Dq + h * DKq + 2 * (lane & 3);
#pragma unroll
    for (int nt = 0; nt < 8; nt++) {
        float x0 = oacc[nt][0] * i0, x1 = oacc[nt][1] * i0;
        float y0 = oacc[nt][2] * i1, y1 = oacc[nt][3] * i1;
        float hx0 = __bfloat162float(__float2bfloat16(x0));
        float hx1 = __bfloat162float(__float2bfloat16(x1));
        float hy0 = __bfloat162float(__float2bfloat16(y0));
        float hy1 = __bfloat162float(__float2bfloat16(y1));
        size_t o0 = ob0 + nt * 8;
        size_t o1 = o0 + 8 * (size_t)Dq;
        *(uint32_t*)(AOh + o0) = pack_bf16(hx0, hx1);
        *(uint32_t*)(AOl + o0) = pack_bf16(x0 - hx0, x1 - hx1);
        *(uint32_t*)(AOh + o1) = pack_bf16(hy0, hy1);
        *(uint32_t*)(AOl + o1) = pack_bf16(y0 - hy0, y1 - hy1);
    }
}

// ---------------------------------------------------------------------------
extern "C" void kernel_launch(void* const* d_in, const int* in_sizes, int n_in,
                              void* d_out, int out_size)
{
    const float* x    = (const float*)d_in[0];
    const float* W_Q  = (const float*)d_in[1];
    const float* W_K  = (const float*)d_in[2];
    const float* W_V  = (const float*)d_in[3];
    const float* W_O  = (const float*)d_in[4];
    const float* gain = (const float*)d_in[5];
    float* out = (float*)d_out;

    float *Qp, *Kp, *sinp, *cosp;
    __nv_bfloat16 *xh, *xl, *aoh, *aol, *Wh, *Wl;
    __nv_bfloat16 *qh, *ql, *kh, *kl, *vh, *vl;
    cudaGetSymbolAddress((void**)&Qp,   g_Q);
    cudaGetSymbolAddress((void**)&Kp,   g_K);
    cudaGetSymbolAddress((void**)&sinp, g_sin);
    cudaGetSymbolAddress((void**)&cosp, g_cos);
    cudaGetSymbolAddress((void**)&xh,   g_xh);
    cudaGetSymbolAddress((void**)&xl,   g_xl);
    cudaGetSymbolAddress((void**)&aoh,  g_aoh);
    cudaGetSymbolAddress((void**)&aol,  g_aol);
    cudaGetSymbolAddress((void**)&Wh,   g_Wh);
    cudaGetSymbolAddress((void**)&Wl,   g_Wl);
    cudaGetSymbolAddress((void**)&qh,   g_Qh);
    cudaGetSymbolAddress((void**)&ql,   g_Ql);
    cudaGetSymbolAddress((void**)&kh,   g_Kh);
    cudaGetSymbolAddress((void**)&kl,   g_Kl);
    cudaGetSymbolAddress((void**)&vh,   g_Vh);
    cudaGetSymbolAddress((void**)&vl,   g_Vl);

    cudaFuncSetAttribute(gemm_tc<0>,
                         cudaFuncAttributeMaxDynamicSharedMemorySize, GEMM_SMEM);
    cudaFuncSetAttribute(gemm_tc<1>,
                         cudaFuncAttributeMaxDynamicSharedMemorySize, GEMM_SMEM);
    cudaFuncSetAttribute(flash_tc,
                         cudaFuncAttributeMaxDynamicSharedMemorySize, FLASH_SMEM);

    const int nx4 = NR * Dq / 4;
    const int nw4 = Dq * Dq / 4;
    const size_t WSZ = (size_t)Dq * Dq;

    // splits + table
    split_kernel<<<nx4 / 256, 256>>>(x, xh, xl, nx4, 1.f);
    split_kernel<<<nw4 / 256, 256>>>(W_Q, Wh + 0*WSZ, Wl + 0*WSZ, nw4, 1.f);
    split_kernel<<<nw4 / 256, 256>>>(W_K, Wh + 1*WSZ, Wl + 1*WSZ, nw4, 1.f);
    split_kernel<<<nw4 / 256, 256>>>(W_V, Wh + 2*WSZ, Wl + 2*WSZ, nw4, 1.f);
    split_kernel<<<nw4 / 256, 256>>>(W_O, Wh + 3*WSZ, Wl + 3*WSZ, nw4, 1.f);
    rope_table_kernel<<<Sq * 32 / 256, 256>>>(sinp, cosp);

    // projections (Q,K fp32 out; V writes hi/lo directly)
    dim3 gg(Dq / 128, NR / 128);
    gemm_tc<0><<<gg, 256, GEMM_SMEM>>>(xh, xl, Wh + 0*WSZ, Wl + 0*WSZ, Qp, nullptr, nullptr, NR, Dq, Dq);
    gemm_tc<0><<<gg, 256, GEMM_SMEM>>>(xh, xl, Wh + 1*WSZ, Wl + 1*WSZ, Kp, nullptr, nullptr, NR, Dq, Dq);
    gemm_tc<1><<<gg, 256, GEMM_SMEM>>>(xh, xl, Wh + 2*WSZ, Wl + 2*WSZ, nullptr, vh, vl, NR, Dq, Dq);

    // fused norm+rope+split (1/8 folded into Q)
    norm_rope_split<<<NR, 256>>>(Qp, qh, ql, gain, sinp, cosp, 0.125f);
    norm_rope_split<<<NR, 256>>>(Kp, kh, kl, gain, sinp, cosp, 1.f);

    // tensor-core flash attention (64-query CTAs, R4 structure)
    flash_tc<<<dim3(Sq / 64, Hq, Bq), 128, FLASH_SMEM>>>(qh, ql, kh, kl, vh, vl, aoh, aol);

    gemm_tc<0><<<gg, 256, GEMM_SMEM>>>(aoh, aol, Wh + 3*WSZ, Wl + 3*WSZ, out, nullptr, nullptr, NR, Dq, Dq);
}

// round 11
// speedup vs baseline: 1.5281x; 1.0884x over previous
#include <cuda_runtime.h>
#include <cuda_bf16.h>
#include <math.h>
#include <stdint.h>

// Problem constants (fixed by dataset)
#define Bq   2
#define Sq   2048
#define Dq   1024
#define Hq   16
#define DKq  64
#define NR   (Bq*Sq)          // 4096 token rows

// ---------------------------------------------------------------------------
// Scratch (allocation-free rule: __device__ globals)
// ---------------------------------------------------------------------------
__device__ float g_Q [NR*Dq];
__device__ float g_K [NR*Dq];
__device__ __nv_bfloat16 g_xh [NR*Dq];
__device__ __nv_bfloat16 g_xl [NR*Dq];
__device__ __nv_bfloat16 g_aoh[NR*Dq];
__device__ __nv_bfloat16 g_aol[NR*Dq];
__device__ __nv_bfloat16 g_Qh [NR*Dq];
__device__ __nv_bfloat16 g_Ql [NR*Dq];
__device__ __nv_bfloat16 g_Kh [NR*Dq];
__device__ __nv_bfloat16 g_Kl [NR*Dq];
__device__ __nv_bfloat16 g_Vh [NR*Dq];
__device__ __nv_bfloat16 g_Vl [NR*Dq];
__device__ __nv_bfloat16 g_Wh [4*Dq*Dq];   // WQ,WK,WV,WO hi
__device__ __nv_bfloat16 g_Wl [4*Dq*Dq];   // lo
__device__ float g_sin[Sq*32];
__device__ float g_cos[Sq*32];

// ---------------------------------------------------------------------------
// PTX helpers
// ---------------------------------------------------------------------------
__device__ __forceinline__ void mma_bf16(float* d, const uint32_t* a, const uint32_t* b) {
    asm volatile(
        "mma.sync.aligned.m16n8k16.row.col.f32.bf16.bf16.f32 "
        "{%0,%1,%2,%3}, {%4,%5,%6,%7}, {%8,%9}, {%0,%1,%2,%3};\n"
        : "+f"(d[0]), "+f"(d[1]), "+f"(d[2]), "+f"(d[3])
        : "r"(a[0]), "r"(a[1]), "r"(a[2]), "r"(a[3]), "r"(b[0]), "r"(b[1]));
}

__device__ __forceinline__ void ldsm_x4(uint32_t* r, uint32_t addr) {
    asm volatile("ldmatrix.sync.aligned.m8n8.x4.shared.b16 {%0,%1,%2,%3}, [%4];"
        : "=r"(r[0]), "=r"(r[1]), "=r"(r[2]), "=r"(r[3]) : "r"(addr));
}
__device__ __forceinline__ void ldsm_x4_t(uint32_t* r, uint32_t addr) {
    asm volatile("ldmatrix.sync.aligned.m8n8.x4.trans.shared.b16 {%0,%1,%2,%3}, [%4];"
        : "=r"(r[0]), "=r"(r[1]), "=r"(r[2]), "=r"(r[3]) : "r"(addr));
}
__device__ __forceinline__ void ldsm_x2(uint32_t* r, uint32_t addr) {
    asm volatile("ldmatrix.sync.aligned.m8n8.x2.shared.b16 {%0,%1}, [%2];"
        : "=r"(r[0]), "=r"(r[1]) : "r"(addr));
}

__device__ __forceinline__ uint32_t smem_u32(const void* p) {
    uint32_t a;
    asm("{ .reg .u64 t; cvta.to.shared.u64 t, %1; cvt.u32.u64 %0, t; }"
        : "=r"(a) : "l"(p));
    return a;
}

__device__ __forceinline__ uint32_t pack_bf16(float a, float b) {
    __nv_bfloat162 t = __floats2bfloat162_rn(a, b);
    return *reinterpret_cast<uint32_t*>(&t);
}

__device__ __forceinline__ void cp16(uint32_t saddr, const void* gaddr) {
    asm volatile("cp.async.cg.shared.global [%0], [%1], 16;"
        :: "r"(saddr), "l"(gaddr));
}
#define CP_COMMIT() asm volatile("cp.async.commit_group;")
#define CP_WAIT1()  asm volatile("cp.async.wait_group 1;")
#define CP_WAIT0()  asm volatile("cp.async.wait_group 0;")

// ---------------------------------------------------------------------------
// fp32 -> (bf16 hi, bf16 lo) split with scale. One float4 per thread.
// ---------------------------------------------------------------------------
__global__ void __launch_bounds__(256) split_kernel(const float* __restrict__ X,
                                                    __nv_bfloat16* __restrict__ H,
                                                    __nv_bfloat16* __restrict__ L,
                                                    int n4, float scale)
{
    int i = blockIdx.x * 256 + threadIdx.x;
    if (i >= n4) return;
    float4 v = ((const float4*)X)[i];
    float f[4] = {v.x * scale, v.y * scale, v.z * scale, v.w * scale};
    __nv_bfloat16 h[4], l[4];
#pragma unroll
    for (int j = 0; j < 4; j++) {
        h[j] = __float2bfloat16(f[j]);
        l[j] = __float2bfloat16(f[j] - __bfloat162float(h[j]));
    }
    __nv_bfloat162* H2 = (__nv_bfloat162*)H;
    __nv_bfloat162* L2 = (__nv_bfloat162*)L;
    H2[2*i]   = __nv_bfloat162(h[0], h[1]);
    H2[2*i+1] = __nv_bfloat162(h[2], h[3]);
    L2[2*i]   = __nv_bfloat162(l[0], l[1]);
    L2[2*i+1] = __nv_bfloat162(l[2], l[3]);
}

// ---------------------------------------------------------------------------
// Split-bf16 tensor-core GEMM, 2-stage cp.async at K-chunk 32.
// Same 2 CTAs/SM occupancy as the sync version (80 KB total smem),
// plus intra-CTA overlap. MMA order identical to R4/R8 (ks x chunks).
// CTA 128x128, 8 warps of 64x32, 3 passes (AhBh+AlBh+AhBl).
// EPI: 0 -> fp32 C; 1 -> bf16 hi/lo (CH, CL).
// ---------------------------------------------------------------------------
#define GS2   40                          // halfwords per smem row (32 + 8 pad)
#define GT2   (128 * GS2)                 // halfwords per tile (128x32 padded)
#define GSTG  (4 * GT2 * 2)               // bytes per stage (Ah,Al,Bh,Bl)
#define GEMM_SMEM (2 * GSTG)              // 81920 B

template<int EPI>
__global__ void __launch_bounds__(256) gemm_tc(const __nv_bfloat16* __restrict__ Ah,
                                               const __nv_bfloat16* __restrict__ Al,
                                               const __nv_bfloat16* __restrict__ Bh,
                                               const __nv_bfloat16* __restrict__ Bl,
                                               float* __restrict__ C,
                                               __nv_bfloat16* __restrict__ CH,
                                               __nv_bfloat16* __restrict__ CL,
                                               int M, int N, int K)
{
    extern __shared__ __nv_bfloat16 smg[];

    const int tid  = threadIdx.x;
    const int lane = tid & 31;
    const int wid  = tid >> 5;
    const int bm   = blockIdx.y * 128;
    const int bn   = blockIdx.x * 128;
    const int wm   = (wid >> 2) * 64;
    const int wn   = (wid & 3) * 32;

    const uint32_t sb = smem_u32(smg);

    float acc[4][4][4];
#pragma unroll
    for (int mt = 0; mt < 4; mt++)
#pragma unroll
        for (int nt = 0; nt < 4; nt++)
#pragma unroll
            for (int r = 0; r < 4; r++) acc[mt][nt][r] = 0.f;

    const uint32_t offA = ((lane & 15) * GS2 + (lane >> 4) * 8) * 2;
    const uint32_t offB = ((lane & 7) * GS2 + ((lane >> 3) & 1) * 8) * 2;

    // async loader: 4 tiles of 128x32 bf16 into stage s (8 cp16 per thread)
    auto issue = [&](int kt, int s) {
        const int k0 = kt * 32;
        const uint32_t stb = sb + s * GSTG;
#pragma unroll
        for (int j = 0; j < 2; j++) {
            int idx = tid + j * 256;          // 0..511
            int row = idx >> 2;               // 0..127
            int cq  = idx & 3;                // 4 chunks of 8 halfwords
            uint32_t so = (uint32_t)(row * GS2 + cq * 8) * 2;
            size_t ga = (size_t)(bm + row) * K + k0 + cq * 8;
            size_t gb = (size_t)(bn + row) * K + k0 + cq * 8;
            cp16(stb              + so, Ah + ga);
            cp16(stb + GT2 * 2    + so, Al + ga);
            cp16(stb + 2 * GT2 * 2 + so, Bh + gb);
            cp16(stb + 3 * GT2 * 2 + so, Bl + gb);
        }
        CP_COMMIT();
    };

    const int KT = K / 32;
    issue(0, 0);

    for (int kt = 0; kt < KT; kt++) {
        if (kt + 1 < KT) {
            issue(kt + 1, (kt + 1) & 1);
            CP_WAIT1();                       // current stage resident, prefetch in flight
        } else {
            CP_WAIT0();
        }
        __syncthreads();

        const uint32_t stb = sb + (kt & 1) * GSTG;
        const uint32_t aAh = stb;
        const uint32_t aAl = stb + GT2 * 2;
        const uint32_t aBh = stb + 2 * GT2 * 2;
        const uint32_t aBl = stb + 3 * GT2 * 2;

#pragma unroll
        for (int ks = 0; ks < 2; ks++) {
            const uint32_t kof = (uint32_t)(ks * 16 * 2);
            uint32_t bh[4][2], bl[4][2], af[4][4];
#pragma unroll
            for (int nt = 0; nt < 4; nt++) {
                uint32_t ro = (uint32_t)((wn + nt * 8) * GS2 * 2) + kof;
                ldsm_x2(bh[nt], aBh + ro + offB);
                ldsm_x2(bl[nt], aBl + ro + offB);
            }
#pragma unroll
            for (int mt = 0; mt < 4; mt++) {
                uint32_t ro = (uint32_t)((wm + mt * 16) * GS2 * 2) + kof;
                ldsm_x4(af[mt], aAh + ro + offA);
            }
#pragma unroll
            for (int mt = 0; mt < 4; mt++)
#pragma unroll
                for (int nt = 0; nt < 4; nt++) {
                    mma_bf16(acc[mt][nt], af[mt], bh[nt]);
                    mma_bf16(acc[mt][nt], af[mt], bl[nt]);
                }
#pragma unroll
            for (int mt = 0; mt < 4; mt++) {
                uint32_t ro = (uint32_t)((wm + mt * 16) * GS2 * 2) + kof;
                ldsm_x4(af[mt], aAl + ro + offA);
            }
#pragma unroll
            for (int mt = 0; mt < 4; mt++)
#pragma unroll
                for (int nt = 0; nt < 4; nt++)
                    mma_bf16(acc[mt][nt], af[mt], bh[nt]);
        }
        __syncthreads();                      // readers done before next overwrite
    }

    const int er = lane >> 2;
    const int ec = (lane & 3) * 2;
#pragma unroll
    for (int mt = 0; mt < 4; mt++) {
        const int row = bm + wm + mt * 16 + er;
#pragma unroll
        for (int nt = 0; nt < 4; nt++) {
            const int col = bn + wn + nt * 8 + ec;
            if (EPI == 0) {
                *(float2*)(C + (size_t)row * N + col) =
                    make_float2(acc[mt][nt][0], acc[mt][nt][1]);
                *(float2*)(C + (size_t)(row + 8) * N + col) =
                    make_float2(acc[mt][nt][2], acc[mt][nt][3]);
            } else {
                float v0 = acc[mt][nt][0], v1 = acc[mt][nt][1];
                float v2 = acc[mt][nt][2], v3 = acc[mt][nt][3];
                float h0 = __bfloat162float(__float2bfloat16(v0));
                float h1 = __bfloat162float(__float2bfloat16(v1));
                float h2 = __bfloat162float(__float2bfloat16(v2));
                float h3 = __bfloat162float(__float2bfloat16(v3));
                *(uint32_t*)(CH + (size_t)row * N + col)       = pack_bf16(h0, h1);
                *(uint32_t*)(CL + (size_t)row * N + col)       = pack_bf16(v0 - h0, v1 - h1);
                *(uint32_t*)(CH + (size_t)(row + 8) * N + col) = pack_bf16(h2, h3);
                *(uint32_t*)(CL + (size_t)(row + 8) * N + col) = pack_bf16(v2 - h2, v3 - h3);
            }
        }
    }
}

// ---------------------------------------------------------------------------
// RoPE table: sin/cos[s][p] for s<2048, p<32.
// ---------------------------------------------------------------------------
__global__ void __launch_bounds__(256) rope_table_kernel(float* __restrict__ st,
                                                         float* __restrict__ ct)
{
    int i = blockIdx.x * 256 + threadIdx.x;
    int s = i >> 5, p = i & 31;
    double f = exp(-(double)p * (9.210340371976184 / 32.0));
    float a = (float)((double)s * f);
    float sv, cv;
    sincosf(a, &sv, &cv);
    st[i] = sv;
    ct[i] = cv;
}

// ---------------------------------------------------------------------------
// Fused RMSNorm + RoPE + bf16 hi/lo split (scale folded). fp32 in, hi/lo out.
// ---------------------------------------------------------------------------
__global__ void __launch_bounds__(256) norm_rope_split(const float* __restrict__ T,
                                                       __nv_bfloat16* __restrict__ H,
                                                       __nv_bfloat16* __restrict__ L,
                                                       const float* __restrict__ gain,
                                                       const float* __restrict__ st,
                                                       const float* __restrict__ ct,
                                                       float scale)
{
    const int n = blockIdx.x;
    const int s = n % Sq;
    const float* row = T + (size_t)n * Dq;
    const int t = threadIdx.x;

    float4 x = ((const float4*)row)[t];
    float ss = x.x * x.x + x.y * x.y + x.z * x.z + x.w * x.w;
#pragma unroll
    for (int o = 16; o > 0; o >>= 1) ss += __shfl_xor_sync(0xffffffffu, ss, o);

    __shared__ float wsum[8];
    if ((t & 31) == 0) wsum[t >> 5] = ss;
    __syncthreads();
    float tot = 0.f;
#pragma unroll
    for (int i = 0; i < 8; i++) tot += wsum[i];

    const float rinv = rsqrtf(tot * (1.0f / 1024.0f) + 1e-5f);
    const float4 g = ((const float4*)gain)[t];

    const int p0 = ((t * 4) & 63) >> 1;
    const float s0 = st[s * 32 + p0],     c0 = ct[s * 32 + p0];
    const float s1 = st[s * 32 + p0 + 1], c1 = ct[s * 32 + p0 + 1];

    const float e0 = x.x * rinv * g.x, o0 = x.y * rinv * g.y;
    const float e1 = x.z * rinv * g.z, o1 = x.w * rinv * g.w;

    float r0 = (e0 * c0 - o0 * s0) * scale;
    float r1 = (o0 * c0 + e0 * s0) * scale;
    float r2 = (e1 * c1 - o1 * s1) * scale;
    float r3 = (o1 * c1 + e1 * s1) * scale;

    float h0 = __bfloat162float(__float2bfloat16(r0));
    float h1 = __bfloat162float(__float2bfloat16(r1));
    float h2 = __bfloat162float(__float2bfloat16(r2));
    float h3 = __bfloat162float(__float2bfloat16(r3));

    uint32_t* H32 = (uint32_t*)(H + (size_t)n * Dq);
    uint32_t* L32 = (uint32_t*)(L + (size_t)n * Dq);
    H32[2*t]   = pack_bf16(h0, h1);
    H32[2*t+1] = pack_bf16(h2, h3);
    L32[2*t]   = pack_bf16(r0 - h0, r1 - h1);
    L32[2*t+1] = pack_bf16(r2 - h2, r3 - h3);
}

// ---------------------------------------------------------------------------
// Tensor-core causal flash attention (proven R4 structure: 64-query CTAs,
// 4 warps, sync smem loads, 4 CTAs/SM). 3-pass split-bf16 QK^T and PV.
// ---------------------------------------------------------------------------
#define FSTR 72
#define FTILE (64 * FSTR)                 // halfwords per 64x64 tile
#define FLASH_SMEM (6 * FTILE * 2)        // Qh,Ql,Kh,Kl,Vh,Vl

__global__ void __launch_bounds__(128) flash_tc(
    const __nv_bfloat16* __restrict__ Qh, const __nv_bfloat16* __restrict__ Ql,
    const __nv_bfloat16* __restrict__ Kh, const __nv_bfloat16* __restrict__ Kl,
    const __nv_bfloat16* __restrict__ Vh, const __nv_bfloat16* __restrict__ Vl,
    __nv_bfloat16* __restrict__ AOh, __nv_bfloat16* __restrict__ AOl)
{
    extern __shared__ __nv_bfloat16 smf[];
    __nv_bfloat16* sQh = smf;
    __nv_bfloat16* sQl = smf + FTILE;
    __nv_bfloat16* sKh = smf + 2 * FTILE;
    __nv_bfloat16* sKl = smf + 3 * FTILE;
    __nv_bfloat16* sVh = smf + 4 * FTILE;
    __nv_bfloat16* sVl = smf + 5 * FTILE;

    const int tid  = threadIdx.x;
    const int lane = tid & 31;
    const int warp = tid >> 5;
    const int q0 = blockIdx.x * 64;
    const int h  = blockIdx.y;
    const int b  = blockIdx.z;

    const uint32_t sb  = smem_u32(smf);
    const uint32_t aQh = sb;
    const uint32_t aQl = sb +     FTILE * 2;
    const uint32_t aKh = sb + 2 * FTILE * 2;
    const uint32_t aKl = sb + 3 * FTILE * 2;
    const uint32_t aVh = sb + 4 * FTILE * 2;
    const uint32_t aVl = sb + 5 * FTILE * 2;

    // ---- load Q tile (64 rows x 64 dims) ----
    {
        const size_t gbase = ((size_t)b * Sq + q0) * Dq + h * DKq;
#pragma unroll
        for (int j = 0; j < 4; j++) {
            int idx = tid + j * 128;          // 0..511
            int row = idx >> 3;
            int cq  = idx & 7;
            size_t g = gbase + (size_t)row * Dq + cq * 8;
            uint32_t so = (uint32_t)(row * FSTR + cq * 8);
            *(uint4*)(sQh + so) = *(const uint4*)(Qh + g);
            *(uint4*)(sQl + so) = *(const uint4*)(Ql + g);
        }
    }
    __syncthreads();

    // ---- Q A-fragments (4 k-chunks) ----
    uint32_t qa_h[4][4], qa_l[4][4];
    const uint32_t offA = (uint32_t)(((lane & 15) * FSTR + (lane >> 4) * 8) * 2);
    const uint32_t qwb  = (uint32_t)(warp * 16 * FSTR * 2);
#pragma unroll
    for (int kc = 0; kc < 4; kc++) {
        ldsm_x4(qa_h[kc], aQh + qwb + (uint32_t)(kc * 32) + offA);
        ldsm_x4(qa_l[kc], aQl + qwb + (uint32_t)(kc * 32) + offA);
    }

    float m0 = -1e30f, m1 = -1e30f, l0 = 0.f, l1 = 0.f;
    float oacc[8][4];
#pragma unroll
    for (int nt = 0; nt < 8; nt++)
#pragma unroll
        for (int r = 0; r < 4; r++) oacc[nt][r] = 0.f;

    const int r0g = q0 + warp * 16 + (lane >> 2);

    const int ntiles = blockIdx.x + 1;
    for (int t = 0; t < ntiles; t++) {
        const int k0 = t * 64;
        __syncthreads();
        {
            const size_t kb = ((size_t)b * Sq + k0) * Dq + h * DKq;
#pragma unroll
            for (int j = 0; j < 4; j++) {
                int idx = tid + j * 128;
                int row = idx >> 3;
                int cq  = idx & 7;
                size_t g = kb + (size_t)row * Dq + cq * 8;
                uint32_t so = (uint32_t)(row * FSTR + cq * 8);
                *(uint4*)(sKh + so) = *(const uint4*)(Kh + g);
                *(uint4*)(sKl + so) = *(const uint4*)(Kl + g);
                *(uint4*)(sVh + so) = *(const uint4*)(Vh + g);
                *(uint4*)(sVl + so) = *(const uint4*)(Vl + g);
            }
        }
        __syncthreads();

        // ---- S = Q K^T ----
        float sacc[8][4];
#pragma unroll
        for (int nt = 0; nt < 8; nt++)
#pragma unroll
            for (int r = 0; r < 4; r++) sacc[nt][r] = 0.f;

#pragma unroll
        for (int nt = 0; nt < 8; nt++) {
            uint32_t kbh[8], kbl[8];
            uint32_t rb = (uint32_t)(((nt * 8 + (lane & 7)) * FSTR + (lane >> 3) * 8) * 2);
            ldsm_x4(kbh,     aKh + rb);
            ldsm_x4(kbh + 4, aKh + rb + 64);
            ldsm_x4(kbl,     aKl + rb);
            ldsm_x4(kbl + 4, aKl + rb + 64);
#pragma unroll
            for (int kc = 0; kc < 4; kc++) {
                mma_bf16(sacc[nt], qa_h[kc], kbh + kc * 2);
                mma_bf16(sacc[nt], qa_l[kc], kbh + kc * 2);
                mma_bf16(sacc[nt], qa_h[kc], kbl + kc * 2);
            }
        }

        // ---- causal mask (diagonal tile only) ----
        if (t == blockIdx.x) {
            const int cb = k0 + 2 * (lane & 3);
#pragma unroll
            for (int nt = 0; nt < 8; nt++) {
                int c = cb + nt * 8;
                if (c     > r0g)     sacc[nt][0] = -1e30f;
                if (c + 1 > r0g)     sacc[nt][1] = -1e30f;
                if (c     > r0g + 8) sacc[nt][2] = -1e30f;
                if (c + 1 > r0g + 8) sacc[nt][3] = -1e30f;
            }
        }

        // ---- online softmax ----
        float mx0 = -1e30f, mx1 = -1e30f;
#pragma unroll
        for (int nt = 0; nt < 8; nt++) {
            mx0 = fmaxf(mx0, fmaxf(sacc[nt][0], sacc[nt][1]));
            mx1 = fmaxf(mx1, fmaxf(sacc[nt][2], sacc[nt][3]));
        }
        mx0 = fmaxf(mx0, __shfl_xor_sync(0xffffffffu, mx0, 1));
        mx0 = fmaxf(mx0, __shfl_xor_sync(0xffffffffu, mx0, 2));
        mx1 = fmaxf(mx1, __shfl_xor_sync(0xffffffffu, mx1, 1));
        mx1 = fmaxf(mx1, __shfl_xor_sync(0xffffffffu, mx1, 2));

        const float m0n = fmaxf(m0, mx0);
        const float m1n = fmaxf(m1, mx1);
        const float a0 = __expf(m0 - m0n);
        const float a1 = __expf(m1 - m1n);

        float rs0 = 0.f, rs1 = 0.f;
#pragma unroll
        for (int nt = 0; nt < 8; nt++) {
            float p0 = __expf(sacc[nt][0] - m0n);
            float p1 = __expf(sacc[nt][1] - m0n);
            float p2 = __expf(sacc[nt][2] - m1n);
            float p3 = __expf(sacc[nt][3] - m1n);
            sacc[nt][0] = p0; sacc[nt][1] = p1; sacc[nt][2] = p2; sacc[nt][3] = p3;
            rs0 += p0 + p1;
            rs1 += p2 + p3;
        }
        rs0 += __shfl_xor_sync(0xffffffffu, rs0, 1);
        rs0 += __shfl_xor_sync(0xffffffffu, rs0, 2);
        rs1 += __shfl_xor_sync(0xffffffffu, rs1, 1);
        rs1 += __shfl_xor_sync(0xffffffffu, rs1, 2);

        l0 = l0 * a0 + rs0;
        l1 = l1 * a1 + rs1;
        m0 = m0n;
        m1 = m1n;
#pragma unroll
        for (int nt = 0; nt < 8; nt++) {
            oacc[nt][0] *= a0; oacc[nt][1] *= a0;
            oacc[nt][2] *= a1; oacc[nt][3] *= a1;
        }

        // ---- P -> A-fragments (hi/lo) ----
        uint32_t pa_h[4][4], pa_l[4][4];
#pragma unroll
        for (int kc = 0; kc < 4; kc++) {
#pragma unroll
            for (int half = 0; half < 2; half++) {
                const float* v = sacc[2 * kc + half];
                float h00 = __bfloat162float(__float2bfloat16(v[0]));
                float h01 = __bfloat162float(__float2bfloat16(v[1]));
                float h10 = __bfloat162float(__float2bfloat16(v[2]));
                float h11 = __bfloat162float(__float2bfloat16(v[3]));
                pa_h[kc][0 + 2 * half] = pack_bf16(h00, h01);
                pa_h[kc][1 + 2 * half] = pack_bf16(h10, h11);
                pa_l[kc][0 + 2 * half] = pack_bf16(v[0] - h00, v[1] - h01);
                pa_l[kc][1 + 2 * half] = pack_bf16(v[2] - h10, v[3] - h11);
            }
        }

        // ---- O += P V ----
#pragma unroll
        for (int np = 0; np < 4; np++) {
#pragma unroll
            for (int kc = 0; kc < 4; kc++) {
                uint32_t vbh[4], vbl[4];
                int g = lane >> 3;
                int key = kc * 16 + (g & 1) * 8 + (lane & 7);
                int dim = np * 16 + (g >> 1) * 8;
                uint32_t ad = (uint32_t)((key * FSTR + dim) * 2);
                ldsm_x4_t(vbh, aVh + ad);
                ldsm_x4_t(vbl, aVl + ad);
                mma_bf16(oacc[2 * np],     pa_h[kc], vbh);
                mma_bf16(oacc[2 * np],     pa_l[kc], vbh);
                mma_bf16(oacc[2 * np],     pa_h[kc], vbl);
                mma_bf16(oacc[2 * np + 1], pa_h[kc], vbh + 2);
                mma_bf16(oacc[2 * np + 1], pa_l[kc], vbh + 2);
                mma_bf16(oacc[2 * np + 1], pa_h[kc], vbl + 2);
            }
        }
    }

    // ---- finalize & store as bf16 hi/lo ----
    const float i0 = 1.f / l0;
    const float i1 = 1.f / l1;
    const size_t ob0 = ((size_t)b * Sq + r0g) * Dq + h * DKq + 2 * (lane & 3);
#pragma unroll
    for (int nt = 0; nt < 8; nt++) {
        float x0 = oacc[nt][0] * i0, x1 = oacc[nt][1] * i0;
        float y0 = oacc[nt][2] * i1, y1 = oacc[nt][3] * i1;
        float hx0 = __bfloat162float(__float2bfloat16(x0));
        float hx1 = __bfloat162float(__float2bfloat16(x1));
        float hy0 = __bfloat162float(__float2bfloat16(y0));
        float hy1 = __bfloat162float(__float2bfloat16(y1));
        size_t o0 = ob0 + nt * 8;
        size_t o1 = o0 + 8 * (size_t)Dq;
        *(uint32_t*)(AOh + o0) = pack_bf16(hx0, hx1);
        *(uint32_t*)(AOl + o0) = pack_bf16(x0 - hx0, x1 - hx1);
        *(uint32_t*)(AOh + o1) = pack_bf16(hy0, hy1);
        *(uint32_t*)(AOl + o1) = pack_bf16(y0 - hy0, y1 - hy1);
    }
}

// ---------------------------------------------------------------------------
extern "C" void kernel_launch(void* const* d_in, const int* in_sizes, int n_in,
                              void* d_out, int out_size)
{
    const float* x    = (const float*)d_in[0];
    const float* W_Q  = (const float*)d_in[1];
    const float* W_K  = (const float*)d_in[2];
    const float* W_V  = (const float*)d_in[3];
    const float* W_O  = (const float*)d_in[4];
    const float* gain = (const float*)d_in[5];
    float* out = (float*)d_out;

    float *Qp, *Kp, *sinp, *cosp;
    __nv_bfloat16 *xh, *xl, *aoh, *aol, *Wh, *Wl;
    __nv_bfloat16 *qh, *ql, *kh, *kl, *vh, *vl;
    cudaGetSymbolAddress((void**)&Qp,   g_Q);
    cudaGetSymbolAddress((void**)&Kp,   g_K);
    cudaGetSymbolAddress((void**)&sinp, g_sin);
    cudaGetSymbolAddress((void**)&cosp, g_cos);
    cudaGetSymbolAddress((void**)&xh,   g_xh);
    cudaGetSymbolAddress((void**)&xl,   g_xl);
    cudaGetSymbolAddress((void**)&aoh,  g_aoh);
    cudaGetSymbolAddress((void**)&aol,  g_aol);
    cudaGetSymbolAddress((void**)&Wh,   g_Wh);
    cudaGetSymbolAddress((void**)&Wl,   g_Wl);
    cudaGetSymbolAddress((void**)&qh,   g_Qh);
    cudaGetSymbolAddress((void**)&ql,   g_Ql);
    cudaGetSymbolAddress((void**)&kh,   g_Kh);
    cudaGetSymbolAddress((void**)&kl,   g_Kl);
    cudaGetSymbolAddress((void**)&vh,   g_Vh);
    cudaGetSymbolAddress((void**)&vl,   g_Vl);

    cudaFuncSetAttribute(gemm_tc<0>,
                         cudaFuncAttributeMaxDynamicSharedMemorySize, GEMM_SMEM);
    cudaFuncSetAttribute(gemm_tc<1>,
                         cudaFuncAttributeMaxDynamicSharedMemorySize, GEMM_SMEM);
    cudaFuncSetAttribute(flash_tc,
                         cudaFuncAttributeMaxDynamicSharedMemorySize, FLASH_SMEM);

    const int nx4 = NR * Dq / 4;
    const int nw4 = Dq * Dq / 4;
    const size_t WSZ = (size_t)Dq * Dq;

    // splits + table
    split_kernel<<<nx4 / 256, 256>>>(x, xh, xl, nx4, 1.f);
    split_kernel<<<nw4 / 256, 256>>>(W_Q, Wh + 0*WSZ, Wl + 0*WSZ, nw4, 1.f);
    split_kernel<<<nw4 / 256, 256>>>(W_K, Wh + 1*WSZ, Wl + 1*WSZ, nw4, 1.f);
    split_kernel<<<nw4 / 256, 256>>>(W_V, Wh + 2*WSZ, Wl + 2*WSZ, nw4, 1.f);
    split_kernel<<<nw4 / 256, 256>>>(W_O, Wh + 3*WSZ, Wl + 3*WSZ, nw4, 1.f);
    rope_table_kernel<<<Sq * 32 / 256, 256>>>(sinp, cosp);

    // projections (Q,K fp32 out; V writes hi/lo directly)
    dim3 gg(Dq / 128, NR / 128);
    gemm_tc<0><<<gg, 256, GEMM_SMEM>>>(xh, xl, Wh + 0*WSZ, Wl + 0*WSZ, Qp, nullptr, nullptr, NR, Dq, Dq);
    gemm_tc<0><<<gg, 256, GEMM_SMEM>>>(xh, xl, Wh + 1*WSZ, Wl + 1*WSZ, Kp, nullptr, nullptr, NR, Dq, Dq);
    gemm_tc<1><<<gg, 256, GEMM_SMEM>>>(xh, xl, Wh + 2*WSZ, Wl + 2*WSZ, nullptr, vh, vl, NR, Dq, Dq);

    // fused norm+rope+split (1/8 folded into Q)
    norm_rope_split<<<NR, 256>>>(Qp, qh, ql, gain, sinp, cosp, 0.125f);
    norm_rope_split<<<NR, 256>>>(Kp, kh, kl, gain, sinp, cosp, 1.f);

    // tensor-core flash attention (64-query CTAs, proven structure)
    flash_tc<<<dim3(Sq / 64, Hq, Bq), 128, FLASH_SMEM>>>(qh, ql, kh, kl, vh, vl, aoh, aol);

    gemm_tc<0><<<gg, 256, GEMM_SMEM>>>(aoh, aol, Wh + 3*WSZ, Wl + 3*WSZ, out, nullptr, nullptr, NR, Dq, Dq);
}

// round 13
// speedup vs baseline: 1.5483x; 1.0132x over previous
#include <cuda_runtime.h>
#include <cuda_bf16.h>
#include <math.h>
#include <stdint.h>

// Problem constants (fixed by dataset)
#define Bq   2
#define Sq   2048
#define Dq   1024
#define Hq   16
#define DKq  64
#define NR   (Bq*Sq)          // 4096 token rows

// ---------------------------------------------------------------------------
// Scratch (allocation-free rule: __device__ globals)
// ---------------------------------------------------------------------------
__device__ float g_Q [NR*Dq];
__device__ float g_K [NR*Dq];
__device__ __nv_bfloat16 g_xh [NR*Dq];
__device__ __nv_bfloat16 g_xl [NR*Dq];
__device__ __nv_bfloat16 g_aoh[NR*Dq];
__device__ __nv_bfloat16 g_aol[NR*Dq];
__device__ __nv_bfloat16 g_Qh [NR*Dq];
__device__ __nv_bfloat16 g_Ql [NR*Dq];
__device__ __nv_bfloat16 g_Kh [NR*Dq];
__device__ __nv_bfloat16 g_Kl [NR*Dq];
__device__ __nv_bfloat16 g_Vh [NR*Dq];
__device__ __nv_bfloat16 g_Vl [NR*Dq];
__device__ __nv_bfloat16 g_Wh [4*Dq*Dq];   // WQ,WK,WV,WO hi
__device__ __nv_bfloat16 g_Wl [4*Dq*Dq];   // lo
__device__ float g_sin[Sq*32];
__device__ float g_cos[Sq*32];

// ---------------------------------------------------------------------------
// PTX helpers
// ---------------------------------------------------------------------------
__device__ __forceinline__ void mma_bf16(float* d, const uint32_t* a, const uint32_t* b) {
    asm volatile(
        "mma.sync.aligned.m16n8k16.row.col.f32.bf16.bf16.f32 "
        "{%0,%1,%2,%3}, {%4,%5,%6,%7}, {%8,%9}, {%0,%1,%2,%3};\n"
        : "+f"(d[0]), "+f"(d[1]), "+f"(d[2]), "+f"(d[3])
        : "r"(a[0]), "r"(a[1]), "r"(a[2]), "r"(a[3]), "r"(b[0]), "r"(b[1]));
}

__device__ __forceinline__ void ldsm_x4(uint32_t* r, uint32_t addr) {
    asm volatile("ldmatrix.sync.aligned.m8n8.x4.shared.b16 {%0,%1,%2,%3}, [%4];"
        : "=r"(r[0]), "=r"(r[1]), "=r"(r[2]), "=r"(r[3]) : "r"(addr));
}
__device__ __forceinline__ void ldsm_x4_t(uint32_t* r, uint32_t addr) {
    asm volatile("ldmatrix.sync.aligned.m8n8.x4.trans.shared.b16 {%0,%1,%2,%3}, [%4];"
        : "=r"(r[0]), "=r"(r[1]), "=r"(r[2]), "=r"(r[3]) : "r"(addr));
}
__device__ __forceinline__ void ldsm_x2(uint32_t* r, uint32_t addr) {
    asm volatile("ldmatrix.sync.aligned.m8n8.x2.shared.b16 {%0,%1}, [%2];"
        : "=r"(r[0]), "=r"(r[1]) : "r"(addr));
}

__device__ __forceinline__ uint32_t smem_u32(const void* p) {
    uint32_t a;
    asm("{ .reg .u64 t; cvta.to.shared.u64 t, %1; cvt.u32.u64 %0, t; }"
        : "=r"(a) : "l"(p));
    return a;
}

__device__ __forceinline__ uint32_t pack_bf16(float a, float b) {
    __nv_bfloat162 t = __floats2bfloat162_rn(a, b);
    return *reinterpret_cast<uint32_t*>(&t);
}

__device__ __forceinline__ void cp16(uint32_t saddr, const void* gaddr) {
    asm volatile("cp.async.cg.shared.global [%0], [%1], 16;"
        :: "r"(saddr), "l"(gaddr));
}
#define CP_COMMIT() asm volatile("cp.async.commit_group;")
#define CP_WAIT1()  asm volatile("cp.async.wait_group 1;")
#define CP_WAIT0()  asm volatile("cp.async.wait_group 0;")

// ---------------------------------------------------------------------------
// fp32 -> (bf16 hi, bf16 lo) split with scale. One float4 per thread.
// ---------------------------------------------------------------------------
__global__ void __launch_bounds__(256) split_kernel(const float* __restrict__ X,
                                                    __nv_bfloat16* __restrict__ H,
                                                    __nv_bfloat16* __restrict__ L,
                                                    int n4, float scale)
{
    int i = blockIdx.x * 256 + threadIdx.x;
    if (i >= n4) return;
    float4 v = ((const float4*)X)[i];
    float f[4] = {v.x * scale, v.y * scale, v.z * scale, v.w * scale};
    __nv_bfloat16 h[4], l[4];
#pragma unroll
    for (int j = 0; j < 4; j++) {
        h[j] = __float2bfloat16(f[j]);
        l[j] = __float2bfloat16(f[j] - __bfloat162float(h[j]));
    }
    __nv_bfloat162* H2 = (__nv_bfloat162*)H;
    __nv_bfloat162* L2 = (__nv_bfloat162*)L;
    H2[2*i]   = __nv_bfloat162(h[0], h[1]);
    H2[2*i+1] = __nv_bfloat162(h[2], h[3]);
    L2[2*i]   = __nv_bfloat162(l[0], l[1]);
    L2[2*i+1] = __nv_bfloat162(l[2], l[3]);
}

// ---------------------------------------------------------------------------
// Split-bf16 tensor-core GEMM, 2-stage cp.async at K-chunk 32 (R11 winner).
// ---------------------------------------------------------------------------
#define GS2   40
#define GT2   (128 * GS2)
#define GSTG  (4 * GT2 * 2)
#define GEMM_SMEM (2 * GSTG)

template<int EPI>
__global__ void __launch_bounds__(256) gemm_tc(const __nv_bfloat16* __restrict__ Ah,
                                               const __nv_bfloat16* __restrict__ Al,
                                               const __nv_bfloat16* __restrict__ Bh,
                                               const __nv_bfloat16* __restrict__ Bl,
                                               float* __restrict__ C,
                                               __nv_bfloat16* __restrict__ CH,
                                               __nv_bfloat16* __restrict__ CL,
                                               int M, int N, int K)
{
    extern __shared__ __nv_bfloat16 smg[];

    const int tid  = threadIdx.x;
    const int lane = tid & 31;
    const int wid  = tid >> 5;
    const int bm   = blockIdx.y * 128;
    const int bn   = blockIdx.x * 128;
    const int wm   = (wid >> 2) * 64;
    const int wn   = (wid & 3) * 32;

    const uint32_t sb = smem_u32(smg);

    float acc[4][4][4];
#pragma unroll
    for (int mt = 0; mt < 4; mt++)
#pragma unroll
        for (int nt = 0; nt < 4; nt++)
#pragma unroll
            for (int r = 0; r < 4; r++) acc[mt][nt][r] = 0.f;

    const uint32_t offA = ((lane & 15) * GS2 + (lane >> 4) * 8) * 2;
    const uint32_t offB = ((lane & 7) * GS2 + ((lane >> 3) & 1) * 8) * 2;

    auto issue = [&](int kt, int s) {
        const int k0 = kt * 32;
        const uint32_t stb = sb + s * GSTG;
#pragma unroll
        for (int j = 0; j < 2; j++) {
            int idx = tid + j * 256;
            int row = idx >> 2;
            int cq  = idx & 3;
            uint32_t so = (uint32_t)(row * GS2 + cq * 8) * 2;
            size_t ga = (size_t)(bm + row) * K + k0 + cq * 8;
            size_t gb = (size_t)(bn + row) * K + k0 + cq * 8;
            cp16(stb              + so, Ah + ga);
            cp16(stb + GT2 * 2    + so, Al + ga);
            cp16(stb + 2 * GT2 * 2 + so, Bh + gb);
            cp16(stb + 3 * GT2 * 2 + so, Bl + gb);
        }
        CP_COMMIT();
    };

    const int KT = K / 32;
    issue(0, 0);

    for (int kt = 0; kt < KT; kt++) {
        if (kt + 1 < KT) {
            issue(kt + 1, (kt + 1) & 1);
            CP_WAIT1();
        } else {
            CP_WAIT0();
        }
        __syncthreads();

        const uint32_t stb = sb + (kt & 1) * GSTG;
        const uint32_t aAh = stb;
        const uint32_t aAl = stb + GT2 * 2;
        const uint32_t aBh = stb + 2 * GT2 * 2;
        const uint32_t aBl = stb + 3 * GT2 * 2;

#pragma unroll
        for (int ks = 0; ks < 2; ks++) {
            const uint32_t kof = (uint32_t)(ks * 16 * 2);
            uint32_t bh[4][2], bl[4][2], af[4][4];
#pragma unroll
            for (int nt = 0; nt < 4; nt++) {
                uint32_t ro = (uint32_t)((wn + nt * 8) * GS2 * 2) + kof;
                ldsm_x2(bh[nt], aBh + ro + offB);
                ldsm_x2(bl[nt], aBl + ro + offB);
            }
#pragma unroll
            for (int mt = 0; mt < 4; mt++) {
                uint32_t ro = (uint32_t)((wm + mt * 16) * GS2 * 2) + kof;
                ldsm_x4(af[mt], aAh + ro + offA);
            }
#pragma unroll
            for (int mt = 0; mt < 4; mt++)
#pragma unroll
                for (int nt = 0; nt < 4; nt++) {
                    mma_bf16(acc[mt][nt], af[mt], bh[nt]);
                    mma_bf16(acc[mt][nt], af[mt], bl[nt]);
                }
#pragma unroll
            for (int mt = 0; mt < 4; mt++) {
                uint32_t ro = (uint32_t)((wm + mt * 16) * GS2 * 2) + kof;
                ldsm_x4(af[mt], aAl + ro + offA);
            }
#pragma unroll
            for (int mt = 0; mt < 4; mt++)
#pragma unroll
                for (int nt = 0; nt < 4; nt++)
                    mma_bf16(acc[mt][nt], af[mt], bh[nt]);
        }
        __syncthreads();
    }

    const int er = lane >> 2;
    const int ec = (lane & 3) * 2;
#pragma unroll
    for (int mt = 0; mt < 4; mt++) {
        const int row = bm + wm + mt * 16 + er;
#pragma unroll
        for (int nt = 0; nt < 4; nt++) {
            const int col = bn + wn + nt * 8 + ec;
            if (EPI == 0) {
                *(float2*)(C + (size_t)row * N + col) =
                    make_float2(acc[mt][nt][0], acc[mt][nt][1]);
                *(float2*)(C + (size_t)(row + 8) * N + col) =
                    make_float2(acc[mt][nt][2], acc[mt][nt][3]);
            } else {
                float v0 = acc[mt][nt][0], v1 = acc[mt][nt][1];
                float v2 = acc[mt][nt][2], v3 = acc[mt][nt][3];
                float h0 = __bfloat162float(__float2bfloat16(v0));
                float h1 = __bfloat162float(__float2bfloat16(v1));
                float h2 = __bfloat162float(__float2bfloat16(v2));
                float h3 = __bfloat162float(__float2bfloat16(v3));
                *(uint32_t*)(CH + (size_t)row * N + col)       = pack_bf16(h0, h1);
                *(uint32_t*)(CL + (size_t)row * N + col)       = pack_bf16(v0 - h0, v1 - h1);
                *(uint32_t*)(CH + (size_t)(row + 8) * N + col) = pack_bf16(h2, h3);
                *(uint32_t*)(CL + (size_t)(row + 8) * N + col) = pack_bf16(v2 - h2, v3 - h3);
            }
        }
    }
}

// ---------------------------------------------------------------------------
// RoPE table: sin/cos[s][p] for s<2048, p<32.
// ---------------------------------------------------------------------------
__global__ void __launch_bounds__(256) rope_table_kernel(float* __restrict__ st,
                                                         float* __restrict__ ct)
{
    int i = blockIdx.x * 256 + threadIdx.x;
    int s = i >> 5, p = i & 31;
    double f = exp(-(double)p * (9.210340371976184 / 32.0));
    float a = (float)((double)s * f);
    float sv, cv;
    sincosf(a, &sv, &cv);
    st[i] = sv;
    ct[i] = cv;
}

// ---------------------------------------------------------------------------
// Fused RMSNorm + RoPE + bf16 hi/lo split (scale folded). fp32 in, hi/lo out.
// ---------------------------------------------------------------------------
__global__ void __launch_bounds__(256) norm_rope_split(const float* __restrict__ T,
                                                       __nv_bfloat16* __restrict__ H,
                                                       __nv_bfloat16* __restrict__ L,
                                                       const float* __restrict__ gain,
                                                       const float* __restrict__ st,
                                                       const float* __restrict__ ct,
                                                       float scale)
{
    const int n = blockIdx.x;
    const int s = n % Sq;
    const float* row = T + (size_t)n * Dq;
    const int t = threadIdx.x;

    float4 x = ((const float4*)row)[t];
    float ss = x.x * x.x + x.y * x.y + x.z * x.z + x.w * x.w;
#pragma unroll
    for (int o = 16; o > 0; o >>= 1) ss += __shfl_xor_sync(0xffffffffu, ss, o);

    __shared__ float wsum[8];
    if ((t & 31) == 0) wsum[t >> 5] = ss;
    __syncthreads();
    float tot = 0.f;
#pragma unroll
    for (int i = 0; i < 8; i++) tot += wsum[i];

    const float rinv = rsqrtf(tot * (1.0f / 1024.0f) + 1e-5f);
    const float4 g = ((const float4*)gain)[t];

    const int p0 = ((t * 4) & 63) >> 1;
    const float s0 = st[s * 32 + p0],     c0 = ct[s * 32 + p0];
    const float s1 = st[s * 32 + p0 + 1], c1 = ct[s * 32 + p0 + 1];

    const float e0 = x.x * rinv * g.x, o0 = x.y * rinv * g.y;
    const float e1 = x.z * rinv * g.z, o1 = x.w * rinv * g.w;

    float r0 = (e0 * c0 - o0 * s0) * scale;
    float r1 = (o0 * c0 + e0 * s0) * scale;
    float r2 = (e1 * c1 - o1 * s1) * scale;
    float r3 = (o1 * c1 + e1 * s1) * scale;

    float h0 = __bfloat162float(__float2bfloat16(r0));
    float h1 = __bfloat162float(__float2bfloat16(r1));
    float h2 = __bfloat162float(__float2bfloat16(r2));
    float h3 = __bfloat162float(__float2bfloat16(r3));

    uint32_t* H32 = (uint32_t*)(H + (size_t)n * Dq);
    uint32_t* L32 = (uint32_t*)(L + (size_t)n * Dq);
    H32[2*t]   = pack_bf16(h0, h1);
    H32[2*t+1] = pack_bf16(h2, h3);
    L32[2*t]   = pack_bf16(r0 - h0, r1 - h1);
    L32[2*t+1] = pack_bf16(r2 - h2, r3 - h3);
}

// ---------------------------------------------------------------------------
// Tensor-core causal flash attention, 64-query CTAs, 4 warps,
// 32-key K/V chunks with 2-stage cp.async at UNCHANGED smem (55,296 B)
// -> same 4 CTAs/SM as R11 plus intra-CTA load/compute overlap.
// 3-pass split-bf16 QK^T and PV.
// ---------------------------------------------------------------------------
#define FSTR 72
#define FQ   (64 * FSTR)                  // halfwords per 64x64 Q tile
#define FK   (32 * FSTR)                  // halfwords per 32x64 K/V chunk
#define FSTG_B (4 * FK * 2)               // bytes per stage (Kh,Kl,Vh,Vl)
#define FLASH_SMEM (2 * FQ * 2 + 2 * FSTG_B)   // 55,296 B

__global__ void __launch_bounds__(128) flash_tc(
    const __nv_bfloat16* __restrict__ Qh, const __nv_bfloat16* __restrict__ Ql,
    const __nv_bfloat16* __restrict__ Kh, const __nv_bfloat16* __restrict__ Kl,
    const __nv_bfloat16* __restrict__ Vh, const __nv_bfloat16* __restrict__ Vl,
    __nv_bfloat16* __restrict__ AOh, __nv_bfloat16* __restrict__ AOl)
{
    extern __shared__ __nv_bfloat16 smf[];

    const int tid  = threadIdx.x;
    const int lane = tid & 31;
    const int warp = tid >> 5;
    const int q0 = blockIdx.x * 64;
    const int h  = blockIdx.y;
    const int b  = blockIdx.z;

    const uint32_t sb   = smem_u32(smf);
    const uint32_t aQh  = sb;
    const uint32_t aQl  = sb + FQ * 2;
    const uint32_t kvsb = sb + 2 * FQ * 2;   // stage 0 base

    const size_t kvbase = ((size_t)b * Sq) * Dq + h * DKq;

    // async loader: one 32-key chunk (Kh,Kl,Vh,Vl) into stage s
    auto issue_kv = [&](int c, int s) {
        const int k0 = c * 32;
        const uint32_t stb = kvsb + s * FSTG_B;
#pragma unroll
        for (int j = 0; j < 8; j++) {
            int idx = tid + j * 128;          // 0..1023
            int tile = idx >> 8;              // 0..3 (Kh,Kl,Vh,Vl)
            int row  = (idx >> 3) & 31;
            int cq   = idx & 7;
            uint32_t so = stb + (uint32_t)(tile * FK * 2) +
                          (uint32_t)(row * FSTR + cq * 8) * 2;
            size_t g = kvbase + (size_t)(k0 + row) * Dq + cq * 8;
            const __nv_bfloat16* src =
                (tile == 0) ? (Kh + g) : (tile == 1) ? (Kl + g)
              : (tile == 2) ? (Vh + g) : (Vl + g);
            cp16(so, src);
        }
        CP_COMMIT();
    };

    issue_kv(0, 0);

    // ---- load Q tile (64 rows x 64 dims) ----
    {
        const size_t gbase = ((size_t)b * Sq + q0) * Dq + h * DKq;
        __nv_bfloat16* sQh = smf;
        __nv_bfloat16* sQl = smf + FQ;
#pragma unroll
        for (int j = 0; j < 4; j++) {
            int idx = tid + j * 128;          // 0..511
            int row = idx >> 3;
            int cq  = idx & 7;
            size_t g = gbase + (size_t)row * Dq + cq * 8;
            uint32_t so = (uint32_t)(row * FSTR + cq * 8);
            *(uint4*)(sQh + so) = *(const uint4*)(Qh + g);
            *(uint4*)(sQl + so) = *(const uint4*)(Ql + g);
        }
    }
    __syncthreads();

    // ---- Q A-fragments (4 k-chunks) ----
    uint32_t qa_h[4][4], qa_l[4][4];
    const uint32_t offA = (uint32_t)(((lane & 15) * FSTR + (lane >> 4) * 8) * 2);
    const uint32_t qwb  = (uint32_t)(warp * 16 * FSTR * 2);
#pragma unroll
    for (int kc = 0; kc < 4; kc++) {
        ldsm_x4(qa_h[kc], aQh + qwb + (uint32_t)(kc * 32) + offA);
        ldsm_x4(qa_l[kc], aQl + qwb + (uint32_t)(kc * 32) + offA);
    }

    float m0 = -1e30f, m1 = -1e30f, l0 = 0.f, l1 = 0.f;
    float oacc[8][4];
#pragma unroll
    for (int nt = 0; nt < 8; nt++)
#pragma unroll
        for (int r = 0; r < 4; r++) oacc[nt][r] = 0.f;

    const int r0g = q0 + warp * 16 + (lane >> 2);

    const int nchunks = 2 * (blockIdx.x + 1);   // causal: keys < q0+64
    for (int c = 0; c < nchunks; c++) {
        const int k0 = c * 32;
        if (c + 1 < nchunks) {
            issue_kv(c + 1, (c + 1) & 1);
            CP_WAIT1();
        } else {
            CP_WAIT0();
        }
        __syncthreads();

        const uint32_t stb = kvsb + (c & 1) * FSTG_B;
        const uint32_t aKh = stb;
        const uint32_t aKl = stb + FK * 2;
        const uint32_t aVh = stb + 2 * FK * 2;
        const uint32_t aVl = stb + 3 * FK * 2;

        // ---- S = Q K^T  (32 keys) ----
        float sacc[4][4];
#pragma unroll
        for (int nt = 0; nt < 4; nt++)
#pragma unroll
            for (int r = 0; r < 4; r++) sacc[nt][r] = 0.f;

#pragma unroll
        for (int nt = 0; nt < 4; nt++) {
            uint32_t kbh[8], kbl[8];
            uint32_t rb = (uint32_t)(((nt * 8 + (lane & 7)) * FSTR + (lane >> 3) * 8) * 2);
            ldsm_x4(kbh,     aKh + rb);
            ldsm_x4(kbh + 4, aKh + rb + 64);
            ldsm_x4(kbl,     aKl + rb);
            ldsm_x4(kbl + 4, aKl + rb + 64);
#pragma unroll
            for (int kc = 0; kc < 4; kc++) {
                mma_bf16(sacc[nt], qa_h[kc], kbh + kc * 2);
                mma_bf16(sacc[nt], qa_l[kc], kbh + kc * 2);
                mma_bf16(sacc[nt], qa_h[kc], kbl + kc * 2);
            }
        }

        // ---- causal mask (chunks intersecting the diagonal) ----
        if (k0 + 31 > r0g) {
            const int cb = k0 + 2 * (lane & 3);
#pragma unroll
            for (int nt = 0; nt < 4; nt++) {
                int cc = cb + nt * 8;
                if (cc     > r0g)     sacc[nt][0] = -1e30f;
                if (cc + 1 > r0g)     sacc[nt][1] = -1e30f;
                if (cc     > r0g + 8) sacc[nt][2] = -1e30f;
                if (cc + 1 > r0g + 8) sacc[nt][3] = -1e30f;
            }
        }

        // ---- online softmax ----
        float mx0 = -1e30f, mx1 = -1e30f;
#pragma unroll
        for (int nt = 0; nt < 4; nt++) {
            mx0 = fmaxf(mx0, fmaxf(sacc[nt][0], sacc[nt][1]));
            mx1 = fmaxf(mx1, fmaxf(sacc[nt][2], sacc[nt][3]));
        }
        mx0 = fmaxf(mx0, __shfl_xor_sync(0xffffffffu, mx0, 1));
        mx0 = fmaxf(mx0, __shfl_xor_sync(0xffffffffu, mx0, 2));
        mx1 = fmaxf(mx1, __shfl_xor_sync(0xffffffffu, mx1, 1));
        mx1 = fmaxf(mx1, __shfl_xor_sync(0xffffffffu, mx1, 2));

        const float m0n = fmaxf(m0, mx0);
        const float m1n = fmaxf(m1, mx1);
        const float a0 = __expf(m0 - m0n);
        const float a1 = __expf(m1 - m1n);

        float rs0 = 0.f, rs1 = 0.f;
#pragma unroll
        for (int nt = 0; nt < 4; nt++) {
            float p0 = __expf(sacc[nt][0] - m0n);
            float p1 = __expf(sacc[nt][1] - m0n);
            float p2 = __expf(sacc[nt][2] - m1n);
            float p3 = __expf(sacc[nt][3] - m1n);
            sacc[nt][0] = p0; sacc[nt][1] = p1; sacc[nt][2] = p2; sacc[nt][3] = p3;
            rs0 += p0 + p1;
            rs1 += p2 + p3;
        }
        rs0 += __shfl_xor_sync(0xffffffffu, rs0, 1);
        rs0 += __shfl_xor_sync(0xffffffffu, rs0, 2);
        rs1 += __shfl_xor_sync(0xffffffffu, rs1, 1);
        rs1 += __shfl_xor_sync(0xffffffffu, rs1, 2);

        l0 = l0 * a0 + rs0;
        l1 = l1 * a1 + rs1;
        m0 = m0n;
        m1 = m1n;
#pragma unroll
        for (int nt = 0; nt < 8; nt++) {
            oacc[nt][0] *= a0; oacc[nt][1] *= a0;
            oacc[nt][2] *= a1; oacc[nt][3] *= a1;
        }

        // ---- P -> A-fragments (hi/lo, 2 key chunks of 16) ----
        uint32_t pa_h[2][4], pa_l[2][4];
#pragma unroll
        for (int kc = 0; kc < 2; kc++) {
#pragma unroll
            for (int half = 0; half < 2; half++) {
                const float* v = sacc[2 * kc + half];
                float h00 = __bfloat162float(__float2bfloat16(v[0]));
                float h01 = __bfloat162float(__float2bfloat16(v[1]));
                float h10 = __bfloat162float(__float2bfloat16(v[2]));
                float h11 = __bfloat162float(__float2bfloat16(v[3]));
                pa_h[kc][0 + 2 * half] = pack_bf16(h00, h01);
                pa_h[kc][1 + 2 * half] = pack_bf16(h10, h11);
                pa_l[kc][0 + 2 * half] = pack_bf16(v[0] - h00, v[1] - h01);
                pa_l[kc][1 + 2 * half] = pack_bf16(v[2] - h10, v[3] - h11);
            }
        }

        // ---- O += P V ----
#pragma unroll
        for (int np = 0; np < 4; np++) {
#pragma unroll
            for (int kc = 0; kc < 2; kc++) {
                uint32_t vbh[4], vbl[4];
                int g = lane >> 3;
                int key = kc * 16 + (g & 1) * 8 + (lane & 7);
                int dim = np * 16 + (g >> 1) * 8;
                uint32_t ad = (uint32_t)((key * FSTR + dim) * 2);
                ldsm_x4_t(vbh, aVh + ad);
                ldsm_x4_t(vbl, aVl + ad);
                mma_bf16(oacc[2 * np],     pa_h[kc], vbh);
                mma_bf16(oacc[2 * np],     pa_l[kc], vbh);
                mma_bf16(oacc[2 * np],     pa_h[kc], vbl);
                mma_bf16(oacc[2 * np + 1], pa_h[kc], vbh + 2);
                mma_bf16(oacc[2 * np + 1], pa_l[kc], vbh + 2);
                mma_bf16(oacc[2 * np + 1], pa_h[kc], vbl + 2);
            }
        }
        __syncthreads();                      // readers done before next overwrite
    }

    // ---- finalize & store as bf16 hi/lo ----
    const float i0 = 1.f / l0;
    const float i1 = 1.f / l1;
    const size_t ob0 = ((size_t)b * Sq + r0g) * Dq + h * DKq + 2 * (lane & 3);
#pragma unroll
    for (int nt = 0; nt < 8; nt++) {
        float x0 = oacc[nt][0] * i0, x1 = oacc[nt][1] * i0;
        float y0 = oacc[nt][2] * i1, y1 = oacc[nt][3] * i1;
        float hx0 = __bfloat162float(__float2bfloat16(x0));
        float hx1 = __bfloat162float(__float2bfloat16(x1));
        float hy0 = __bfloat162float(__float2bfloat16(y0));
        float hy1 = __bfloat162float(__float2bfloat16(y1));
        size_t o0 = ob0 + nt * 8;
        size_t o1 = o0 + 8 * (size_t)Dq;
        *(uint32_t*)(AOh + o0) = pack_bf16(hx0, hx1);
        *(uint32_t*)(AOl + o0) = pack_bf16(x0 - hx0, x1 - hx1);
        *(uint32_t*)(AOh + o1) = pack_bf16(hy0, hy1);
        *(uint32_t*)(AOl + o1) = pack_bf16(y0 - hy0, y1 - hy1);
    }
}

// ---------------------------------------------------------------------------
extern "C" void kernel_launch(void* const* d_in, const int* in_sizes, int n_in,
                              void* d_out, int out_size)
{
    const float* x    = (const float*)d_in[0];
    const float* W_Q  = (const float*)d_in[1];
    const float* W_K  = (const float*)d_in[2];
    const float* W_V  = (const float*)d_in[3];
    const float* W_O  = (const float*)d_in[4];
    const float* gain = (const float*)d_in[5];
    float* out = (float*)d_out;

    float *Qp, *Kp, *sinp, *cosp;
    __nv_bfloat16 *xh, *xl, *aoh, *aol, *Wh, *Wl;
    __nv_bfloat16 *qh, *ql, *kh, *kl, *vh, *vl;
    cudaGetSymbolAddress((void**)&Qp,   g_Q);
    cudaGetSymbolAddress((void**)&Kp,   g_K);
    cudaGetSymbolAddress((void**)&sinp, g_sin);
    cudaGetSymbolAddress((void**)&cosp, g_cos);
    cudaGetSymbolAddress((void**)&xh,   g_xh);
    cudaGetSymbolAddress((void**)&xl,   g_xl);
    cudaGetSymbolAddress((void**)&aoh,  g_aoh);
    cudaGetSymbolAddress((void**)&aol,  g_aol);
    cudaGetSymbolAddress((void**)&Wh,   g_Wh);
    cudaGetSymbolAddress((void**)&Wl,   g_Wl);
    cudaGetSymbolAddress((void**)&qh,   g_Qh);
    cudaGetSymbolAddress((void**)&ql,   g_Ql);
    cudaGetSymbolAddress((void**)&kh,   g_Kh);
    cudaGetSymbolAddress((void**)&kl,   g_Kl);
    cudaGetSymbolAddress((void**)&vh,   g_Vh);
    cudaGetSymbolAddress((void**)&vl,   g_Vl);

    cudaFuncSetAttribute(gemm_tc<0>,
                         cudaFuncAttributeMaxDynamicSharedMemorySize, GEMM_SMEM);
    cudaFuncSetAttribute(gemm_tc<1>,
                         cudaFuncAttributeMaxDynamicSharedMemorySize, GEMM_SMEM);
    cudaFuncSetAttribute(flash_tc,
                         cudaFuncAttributeMaxDynamicSharedMemorySize, FLASH_SMEM);

    const int nx4 = NR * Dq / 4;
    const int nw4 = Dq * Dq / 4;
    const size_t WSZ = (size_t)Dq * Dq;

    // splits + table
    split_kernel<<<nx4 / 256, 256>>>(x, xh, xl, nx4, 1.f);
    split_kernel<<<nw4 / 256, 256>>>(W_Q, Wh + 0*WSZ, Wl + 0*WSZ, nw4, 1.f);
    split_kernel<<<nw4 / 256, 256>>>(W_K, Wh + 1*WSZ, Wl + 1*WSZ, nw4, 1.f);
    split_kernel<<<nw4 / 256, 256>>>(W_V, Wh + 2*WSZ, Wl + 2*WSZ, nw4, 1.f);
    split_kernel<<<nw4 / 256, 256>>>(W_O, Wh + 3*WSZ, Wl + 3*WSZ, nw4, 1.f);
    rope_table_kernel<<<Sq * 32 / 256, 256>>>(sinp, cosp);

    // projections (Q,K fp32 out; V writes hi/lo directly)
    dim3 gg(Dq / 128, NR / 128);
    gemm_tc<0><<<gg, 256, GEMM_SMEM>>>(xh, xl, Wh + 0*WSZ, Wl + 0*WSZ, Qp, nullptr, nullptr, NR, Dq, Dq);
    gemm_tc<0><<<gg, 256, GEMM_SMEM>>>(xh, xl, Wh + 1*WSZ, Wl + 1*WSZ, Kp, nullptr, nullptr, NR, Dq, Dq);
    gemm_tc<1><<<gg, 256, GEMM_SMEM>>>(xh, xl, Wh + 2*WSZ, Wl + 2*WSZ, nullptr, vh, vl, NR, Dq, Dq);

    // fused norm+rope+split (1/8 folded into Q)
    norm_rope_split<<<NR, 256>>>(Qp, qh, ql, gain, sinp, cosp, 0.125f);
    norm_rope_split<<<NR, 256>>>(Kp, kh, kl, gain, sinp, cosp, 1.f);

    // tensor-core flash attention (64-query CTAs, pipelined 32-key chunks)
    flash_tc<<<dim3(Sq / 64, Hq, Bq), 128, FLASH_SMEM>>>(qh, ql, kh, kl, vh, vl, aoh, aol);

    gemm_tc<0><<<gg, 256, GEMM_SMEM>>>(aoh, aol, Wh + 3*WSZ, Wl + 3*WSZ, out, nullptr, nullptr, NR, Dq, Dq);
}

// round 14
// speedup vs baseline: 1.5824x; 1.0220x over previous
#include <cuda_runtime.h>
#include <cuda_bf16.h>
#include <math.h>
#include <stdint.h>

// Problem constants (fixed by dataset)
#define Bq   2
#define Sq   2048
#define Dq   1024
#define Hq   16
#define DKq  64
#define NR   (Bq*Sq)          // 4096 token rows

// ---------------------------------------------------------------------------
// Scratch (allocation-free rule: __device__ globals)
// ---------------------------------------------------------------------------
__device__ float g_Q [NR*Dq];
__device__ float g_K [NR*Dq];
__device__ __nv_bfloat16 g_xh [NR*Dq];
__device__ __nv_bfloat16 g_xl [NR*Dq];
__device__ __nv_bfloat16 g_aoh[NR*Dq];
__device__ __nv_bfloat16 g_aol[NR*Dq];
__device__ __nv_bfloat16 g_Qh [NR*Dq];
__device__ __nv_bfloat16 g_Ql [NR*Dq];
__device__ __nv_bfloat16 g_Kh [NR*Dq];
__device__ __nv_bfloat16 g_Kl [NR*Dq];
__device__ __nv_bfloat16 g_Vh [NR*Dq];
__device__ __nv_bfloat16 g_Vl [NR*Dq];
__device__ __nv_bfloat16 g_Wh [4*Dq*Dq];   // WQ,WK,WV,WO hi
__device__ __nv_bfloat16 g_Wl [4*Dq*Dq];   // lo
__device__ float g_sin[Sq*32];
__device__ float g_cos[Sq*32];

// ---------------------------------------------------------------------------
// PTX helpers
// ---------------------------------------------------------------------------
__device__ __forceinline__ void mma_bf16(float* d, const uint32_t* a, const uint32_t* b) {
    asm volatile(
        "mma.sync.aligned.m16n8k16.row.col.f32.bf16.bf16.f32 "
        "{%0,%1,%2,%3}, {%4,%5,%6,%7}, {%8,%9}, {%0,%1,%2,%3};\n"
        : "+f"(d[0]), "+f"(d[1]), "+f"(d[2]), "+f"(d[3])
        : "r"(a[0]), "r"(a[1]), "r"(a[2]), "r"(a[3]), "r"(b[0]), "r"(b[1]));
}

__device__ __forceinline__ void ldsm_x4(uint32_t* r, uint32_t addr) {
    asm volatile("ldmatrix.sync.aligned.m8n8.x4.shared.b16 {%0,%1,%2,%3}, [%4];"
        : "=r"(r[0]), "=r"(r[1]), "=r"(r[2]), "=r"(r[3]) : "r"(addr));
}
__device__ __forceinline__ void ldsm_x4_t(uint32_t* r, uint32_t addr) {
    asm volatile("ldmatrix.sync.aligned.m8n8.x4.trans.shared.b16 {%0,%1,%2,%3}, [%4];"
        : "=r"(r[0]), "=r"(r[1]), "=r"(r[2]), "=r"(r[3]) : "r"(addr));
}
__device__ __forceinline__ void ldsm_x2(uint32_t* r, uint32_t addr) {
    asm volatile("ldmatrix.sync.aligned.m8n8.x2.shared.b16 {%0,%1}, [%2];"
        : "=r"(r[0]), "=r"(r[1]) : "r"(addr));
}

__device__ __forceinline__ uint32_t smem_u32(const void* p) {
    uint32_t a;
    asm("{ .reg .u64 t; cvta.to.shared.u64 t, %1; cvt.u32.u64 %0, t; }"
        : "=r"(a) : "l"(p));
    return a;
}

__device__ __forceinline__ uint32_t pack_bf16(float a, float b) {
    __nv_bfloat162 t = __floats2bfloat162_rn(a, b);
    return *reinterpret_cast<uint32_t*>(&t);
}

__device__ __forceinline__ void cp16(uint32_t saddr, const void* gaddr) {
    asm volatile("cp.async.cg.shared.global [%0], [%1], 16;"
        :: "r"(saddr), "l"(gaddr));
}
#define CP_COMMIT() asm volatile("cp.async.commit_group;")
#define CP_WAIT1()  asm volatile("cp.async.wait_group 1;")
#define CP_WAIT0()  asm volatile("cp.async.wait_group 0;")

// ---------------------------------------------------------------------------
// fp32 -> (bf16 hi, bf16 lo) split with scale. One float4 per thread.
// ---------------------------------------------------------------------------
__global__ void __launch_bounds__(256) split_kernel(const float* __restrict__ X,
                                                    __nv_bfloat16* __restrict__ H,
                                                    __nv_bfloat16* __restrict__ L,
                                                    int n4, float scale)
{
    int i = blockIdx.x * 256 + threadIdx.x;
    if (i >= n4) return;
    float4 v = ((const float4*)X)[i];
    float f[4] = {v.x * scale, v.y * scale, v.z * scale, v.w * scale};
    __nv_bfloat16 h[4], l[4];
#pragma unroll
    for (int j = 0; j < 4; j++) {
        h[j] = __float2bfloat16(f[j]);
        l[j] = __float2bfloat16(f[j] - __bfloat162float(h[j]));
    }
    __nv_bfloat162* H2 = (__nv_bfloat162*)H;
    __nv_bfloat162* L2 = (__nv_bfloat162*)L;
    H2[2*i]   = __nv_bfloat162(h[0], h[1]);
    H2[2*i+1] = __nv_bfloat162(h[2], h[3]);
    L2[2*i]   = __nv_bfloat162(l[0], l[1]);
    L2[2*i+1] = __nv_bfloat162(l[2], l[3]);
}

// ---------------------------------------------------------------------------
// GEMM mainloop core (2-stage cp.async, K-chunk 32) shared by both kernels.
// ---------------------------------------------------------------------------
#define GS2   40
#define GT2   (128 * GS2)
#define GSTG  (4 * GT2 * 2)
#define GEMM_SMEM (2 * GSTG)

struct GemmAcc { float a[4][4][4]; };

__device__ __forceinline__ void gemm_mainloop(
    const __nv_bfloat16* __restrict__ Ah, const __nv_bfloat16* __restrict__ Al,
    const __nv_bfloat16* __restrict__ Bh, const __nv_bfloat16* __restrict__ Bl,
    int bm, int bn, int K, uint32_t sb, int tid, GemmAcc& acc)
{
    const int lane = tid & 31;
    const int wid  = tid >> 5;
    const int wm   = (wid >> 2) * 64;
    const int wn   = (wid & 3) * 32;

#pragma unroll
    for (int mt = 0; mt < 4; mt++)
#pragma unroll
        for (int nt = 0; nt < 4; nt++)
#pragma unroll
            for (int r = 0; r < 4; r++) acc.a[mt][nt][r] = 0.f;

    const uint32_t offA = ((lane & 15) * GS2 + (lane >> 4) * 8) * 2;
    const uint32_t offB = ((lane & 7) * GS2 + ((lane >> 3) & 1) * 8) * 2;

    auto issue = [&](int kt, int s) {
        const int k0 = kt * 32;
        const uint32_t stb = sb + s * GSTG;
#pragma unroll
        for (int j = 0; j < 2; j++) {
            int idx = tid + j * 256;
            int row = idx >> 2;
            int cq  = idx & 3;
            uint32_t so = (uint32_t)(row * GS2 + cq * 8) * 2;
            size_t ga = (size_t)(bm + row) * K + k0 + cq * 8;
            size_t gb = (size_t)(bn + row) * K + k0 + cq * 8;
            cp16(stb               + so, Ah + ga);
            cp16(stb + GT2 * 2     + so, Al + ga);
            cp16(stb + 2 * GT2 * 2 + so, Bh + gb);
            cp16(stb + 3 * GT2 * 2 + so, Bl + gb);
        }
        CP_COMMIT();
    };

    const int KT = K / 32;
    issue(0, 0);

    for (int kt = 0; kt < KT; kt++) {
        if (kt + 1 < KT) {
            issue(kt + 1, (kt + 1) & 1);
            CP_WAIT1();
        } else {
            CP_WAIT0();
        }
        __syncthreads();

        const uint32_t stb = sb + (kt & 1) * GSTG;
        const uint32_t aAh = stb;
        const uint32_t aAl = stb + GT2 * 2;
        const uint32_t aBh = stb + 2 * GT2 * 2;
        const uint32_t aBl = stb + 3 * GT2 * 2;

#pragma unroll
        for (int ks = 0; ks < 2; ks++) {
            const uint32_t kof = (uint32_t)(ks * 16 * 2);
            uint32_t bh[4][2], bl[4][2], af[4][4];
#pragma unroll
            for (int nt = 0; nt < 4; nt++) {
                uint32_t ro = (uint32_t)((wn + nt * 8) * GS2 * 2) + kof;
                ldsm_x2(bh[nt], aBh + ro + offB);
                ldsm_x2(bl[nt], aBl + ro + offB);
            }
#pragma unroll
            for (int mt = 0; mt < 4; mt++) {
                uint32_t ro = (uint32_t)((wm + mt * 16) * GS2 * 2) + kof;
                ldsm_x4(af[mt], aAh + ro + offA);
            }
#pragma unroll
            for (int mt = 0; mt < 4; mt++)
#pragma unroll
                for (int nt = 0; nt < 4; nt++) {
                    mma_bf16(acc.a[mt][nt], af[mt], bh[nt]);
                    mma_bf16(acc.a[mt][nt], af[mt], bl[nt]);
                }
#pragma unroll
            for (int mt = 0; mt < 4; mt++) {
                uint32_t ro = (uint32_t)((wm + mt * 16) * GS2 * 2) + kof;
                ldsm_x4(af[mt], aAl + ro + offA);
            }
#pragma unroll
            for (int mt = 0; mt < 4; mt++)
#pragma unroll
                for (int nt = 0; nt < 4; nt++)
                    mma_bf16(acc.a[mt][nt], af[mt], bh[nt]);
        }
        __syncthreads();
    }
}

// fp32-epilogue GEMM (used for the WO output projection)
__global__ void __launch_bounds__(256) gemm_tc(const __nv_bfloat16* __restrict__ Ah,
                                               const __nv_bfloat16* __restrict__ Al,
                                               const __nv_bfloat16* __restrict__ Bh,
                                               const __nv_bfloat16* __restrict__ Bl,
                                               float* __restrict__ C,
                                               int M, int N, int K)
{
    extern __shared__ __nv_bfloat16 smg[];
    const int tid = threadIdx.x;
    const int bm  = blockIdx.y * 128;
    const int bn  = blockIdx.x * 128;
    GemmAcc acc;
    gemm_mainloop(Ah, Al, Bh, Bl, bm, bn, K, smem_u32(smg), tid, acc);

    const int lane = tid & 31;
    const int wid  = tid >> 5;
    const int wm   = (wid >> 2) * 64;
    const int wn   = (wid & 3) * 32;
    const int er = lane >> 2;
    const int ec = (lane & 3) * 2;
#pragma unroll
    for (int mt = 0; mt < 4; mt++) {
        const int row = bm + wm + mt * 16 + er;
#pragma unroll
        for (int nt = 0; nt < 4; nt++) {
            const int col = bn + wn + nt * 8 + ec;
            *(float2*)(C + (size_t)row * N + col) =
                make_float2(acc.a[mt][nt][0], acc.a[mt][nt][1]);
            *(float2*)(C + (size_t)(row + 8) * N + col) =
                make_float2(acc.a[mt][nt][2], acc.a[mt][nt][3]);
        }
    }
}

// Fused QKV projection: grid.x covers 3*Dq columns; per-CTA W select.
// w=0 -> Q fp32, w=1 -> K fp32, w=2 -> V bf16 hi/lo.
__global__ void __launch_bounds__(256) gemm_qkv(const __nv_bfloat16* __restrict__ Ah,
                                                const __nv_bfloat16* __restrict__ Al,
                                                const __nv_bfloat16* __restrict__ Wh,
                                                const __nv_bfloat16* __restrict__ Wl,
                                                float* __restrict__ Qp,
                                                float* __restrict__ Kp,
                                                __nv_bfloat16* __restrict__ Vh,
                                                __nv_bfloat16* __restrict__ Vl)
{
    extern __shared__ __nv_bfloat16 smg[];
    const int tid = threadIdx.x;
    const int bm  = blockIdx.y * 128;
    const int bng = blockIdx.x * 128;        // 0..3071
    const int w   = bng >> 10;               // 0..2
    const int bn  = bng & 1023;              // column within the 1024-wide output
    const size_t WSZ = (size_t)Dq * Dq;

    GemmAcc acc;
    gemm_mainloop(Ah, Al, Wh + (size_t)w * WSZ, Wl + (size_t)w * WSZ,
                  bm, bn, Dq, smem_u32(smg), tid, acc);

    const int lane = tid & 31;
    const int wid  = tid >> 5;
    const int wm   = (wid >> 2) * 64;
    const int wn   = (wid & 3) * 32;
    const int er = lane >> 2;
    const int ec = (lane & 3) * 2;

    if (w < 2) {
        float* C = (w == 0) ? Qp : Kp;
#pragma unroll
        for (int mt = 0; mt < 4; mt++) {
            const int row = bm + wm + mt * 16 + er;
#pragma unroll
            for (int nt = 0; nt < 4; nt++) {
                const int col = bn + wn + nt * 8 + ec;
                *(float2*)(C + (size_t)row * Dq + col) =
                    make_float2(acc.a[mt][nt][0], acc.a[mt][nt][1]);
                *(float2*)(C + (size_t)(row + 8) * Dq + col) =
                    make_float2(acc.a[mt][nt][2], acc.a[mt][nt][3]);
            }
        }
    } else {
#pragma unroll
        for (int mt = 0; mt < 4; mt++) {
            const int row = bm + wm + mt * 16 + er;
#pragma unroll
            for (int nt = 0; nt < 4; nt++) {
                const int col = bn + wn + nt * 8 + ec;
                float v0 = acc.a[mt][nt][0], v1 = acc.a[mt][nt][1];
                float v2 = acc.a[mt][nt][2], v3 = acc.a[mt][nt][3];
                float h0 = __bfloat162float(__float2bfloat16(v0));
                float h1 = __bfloat162float(__float2bfloat16(v1));
                float h2 = __bfloat162float(__float2bfloat16(v2));
                float h3 = __bfloat162float(__float2bfloat16(v3));
                *(uint32_t*)(Vh + (size_t)row * Dq + col)       = pack_bf16(h0, h1);
                *(uint32_t*)(Vl + (size_t)row * Dq + col)       = pack_bf16(v0 - h0, v1 - h1);
                *(uint32_t*)(Vh + (size_t)(row + 8) * Dq + col) = pack_bf16(h2, h3);
                *(uint32_t*)(Vl + (size_t)(row + 8) * Dq + col) = pack_bf16(v2 - h2, v3 - h3);
            }
        }
    }
}

// ---------------------------------------------------------------------------
// RoPE table: sin/cos[s][p] for s<2048, p<32.
// ---------------------------------------------------------------------------
__global__ void __launch_bounds__(256) rope_table_kernel(float* __restrict__ st,
                                                         float* __restrict__ ct)
{
    int i = blockIdx.x * 256 + threadIdx.x;
    int s = i >> 5, p = i & 31;
    double f = exp(-(double)p * (9.210340371976184 / 32.0));
    float a = (float)((double)s * f);
    float sv, cv;
    sincosf(a, &sv, &cv);
    st[i] = sv;
    ct[i] = cv;
}

// ---------------------------------------------------------------------------
// Fused RMSNorm + RoPE + bf16 hi/lo split (scale folded). fp32 in, hi/lo out.
// ---------------------------------------------------------------------------
__global__ void __launch_bounds__(256) norm_rope_split(const float* __restrict__ T,
                                                       __nv_bfloat16* __restrict__ H,
                                                       __nv_bfloat16* __restrict__ L,
                                                       const float* __restrict__ gain,
                                                       const float* __restrict__ st,
                                                       const float* __restrict__ ct,
                                                       float scale)
{
    const int n = blockIdx.x;
    const int s = n % Sq;
    const float* row = T + (size_t)n * Dq;
    const int t = threadIdx.x;

    float4 x = ((const float4*)row)[t];
    float ss = x.x * x.x + x.y * x.y + x.z * x.z + x.w * x.w;
#pragma unroll
    for (int o = 16; o > 0; o >>= 1) ss += __shfl_xor_sync(0xffffffffu, ss, o);

    __shared__ float wsum[8];
    if ((t & 31) == 0) wsum[t >> 5] = ss;
    __syncthreads();
    float tot = 0.f;
#pragma unroll
    for (int i = 0; i < 8; i++) tot += wsum[i];

    const float rinv = rsqrtf(tot * (1.0f / 1024.0f) + 1e-5f);
    const float4 g = ((const float4*)gain)[t];

    const int p0 = ((t * 4) & 63) >> 1;
    const float s0 = st[s * 32 + p0],     c0 = ct[s * 32 + p0];
    const float s1 = st[s * 32 + p0 + 1], c1 = ct[s * 32 + p0 + 1];

    const float e0 = x.x * rinv * g.x, o0 = x.y * rinv * g.y;
    const float e1 = x.z * rinv * g.z, o1 = x.w * rinv * g.w;

    float r0 = (e0 * c0 - o0 * s0) * scale;
    float r1 = (o0 * c0 + e0 * s0) * scale;
    float r2 = (e1 * c1 - o1 * s1) * scale;
    float r3 = (o1 * c1 + e1 * s1) * scale;

    float h0 = __bfloat162float(__float2bfloat16(r0));
    float h1 = __bfloat162float(__float2bfloat16(r1));
    float h2 = __bfloat162float(__float2bfloat16(r2));
    float h3 = __bfloat162float(__float2bfloat16(r3));

    uint32_t* H32 = (uint32_t*)(H + (size_t)n * Dq);
    uint32_t* L32 = (uint32_t*)(L + (size_t)n * Dq);
    H32[2*t]   = pack_bf16(h0, h1);
    H32[2*t+1] = pack_bf16(h2, h3);
    L32[2*t]   = pack_bf16(r0 - h0, r1 - h1);
    L32[2*t+1] = pack_bf16(r2 - h2, r3 - h3);
}

// ---------------------------------------------------------------------------
// Tensor-core causal flash attention (R13 winner) + heaviest-first remap.
// 64-query CTAs, 4 warps, 32-key cp.async chunks, 55,296 B smem, 4 CTAs/SM.
// ---------------------------------------------------------------------------
#define FSTR 72
#define FQ   (64 * FSTR)
#define FK   (32 * FSTR)
#define FSTG_B (4 * FK * 2)
#define FLASH_SMEM (2 * FQ * 2 + 2 * FSTG_B)   // 55,296 B

__global__ void __launch_bounds__(128) flash_tc(
    const __nv_bfloat16* __restrict__ Qh, const __nv_bfloat16* __restrict__ Ql,
    const __nv_bfloat16* __restrict__ Kh, const __nv_bfloat16* __restrict__ Kl,
    const __nv_bfloat16* __restrict__ Vh, const __nv_bfloat16* __restrict__ Vl,
    __nv_bfloat16* __restrict__ AOh, __nv_bfloat16* __restrict__ AOl)
{
    extern __shared__ __nv_bfloat16 smf[];

    const int tid  = threadIdx.x;
    const int lane = tid & 31;
    const int warp = tid >> 5;
    const int qtile = (int)gridDim.x - 1 - (int)blockIdx.x;   // heaviest first
    const int q0 = qtile * 64;
    const int h  = blockIdx.y;
    const int b  = blockIdx.z;

    const uint32_t sb   = smem_u32(smf);
    const uint32_t aQh  = sb;
    const uint32_t aQl  = sb + FQ * 2;
    const uint32_t kvsb = sb + 2 * FQ * 2;

    const size_t kvbase = ((size_t)b * Sq) * Dq + h * DKq;

    auto issue_kv = [&](int c, int s) {
        const int k0 = c * 32;
        const uint32_t stb = kvsb + s * FSTG_B;
#pragma unroll
        for (int j = 0; j < 8; j++) {
            int idx = tid + j * 128;
            int tile = idx >> 8;
            int row  = (idx >> 3) & 31;
            int cq   = idx & 7;
            uint32_t so = stb + (uint32_t)(tile * FK * 2) +
                          (uint32_t)(row * FSTR + cq * 8) * 2;
            size_t g = kvbase + (size_t)(k0 + row) * Dq + cq * 8;
            const __nv_bfloat16* src =
                (tile == 0) ? (Kh + g) : (tile == 1) ? (Kl + g)
              : (tile == 2) ? (Vh + g) : (Vl + g);
            cp16(so, src);
        }
        CP_COMMIT();
    };

    issue_kv(0, 0);

    {
        const size_t gbase = ((size_t)b * Sq + q0) * Dq + h * DKq;
        __nv_bfloat16* sQh = smf;
        __nv_bfloat16* sQl = smf + FQ;
#pragma unroll
        for (int j = 0; j < 4; j++) {
            int idx = tid + j * 128;
            int row = idx >> 3;
            int cq  = idx & 7;
            size_t g = gbase + (size_t)row * Dq + cq * 8;
            uint32_t so = (uint32_t)(row * FSTR + cq * 8);
            *(uint4*)(sQh + so) = *(const uint4*)(Qh + g);
            *(uint4*)(sQl + so) = *(const uint4*)(Ql + g);
        }
    }
    __syncthreads();

    uint32_t qa_h[4][4], qa_l[4][4];
    const uint32_t offA = (uint32_t)(((lane & 15) * FSTR + (lane >> 4) * 8) * 2);
    const uint32_t qwb  = (uint32_t)(warp * 16 * FSTR * 2);
#pragma unroll
    for (int kc = 0; kc < 4; kc++) {
        ldsm_x4(qa_h[kc], aQh + qwb + (uint32_t)(kc * 32) + offA);
        ldsm_x4(qa_l[kc], aQl + qwb + (uint32_t)(kc * 32) + offA);
    }

    float m0 = -1e30f, m1 = -1e30f, l0 = 0.f, l1 = 0.f;
    float oacc[8][4];
#pragma unroll
    for (int nt = 0; nt < 8; nt++)
#pragma unroll
        for (int r = 0; r < 4; r++) oacc[nt][r] = 0.f;

    const int r0g = q0 + warp * 16 + (lane >> 2);

    const int nchunks = 2 * (qtile + 1);
    for (int c = 0; c < nchunks; c++) {
        const int k0 = c * 32;
        if (c + 1 < nchunks) {
            issue_kv(c + 1, (c + 1) & 1);
            CP_WAIT1();
        } else {
            CP_WAIT0();
        }
        __syncthreads();

        const uint32_t stb = kvsb + (c & 1) * FSTG_B;
        const uint32_t aKh = stb;
        const uint32_t aKl = stb + FK * 2;
        const uint32_t aVh = stb + 2 * FK * 2;
        const uint32_t aVl = stb + 3 * FK * 2;

        float sacc[4][4];
#pragma unroll
        for (int nt = 0; nt < 4; nt++)
#pragma unroll
            for (int r = 0; r < 4; r++) sacc[nt][r] = 0.f;

#pragma unroll
        for (int nt = 0; nt < 4; nt++) {
            uint32_t kbh[8], kbl[8];
            uint32_t rb = (uint32_t)(((nt * 8 + (lane & 7)) * FSTR + (lane >> 3) * 8) * 2);
            ldsm_x4(kbh,     aKh + rb);
            ldsm_x4(kbh + 4, aKh + rb + 64);
            ldsm_x4(kbl,     aKl + rb);
            ldsm_x4(kbl + 4, aKl + rb + 64);
#pragma unroll
            for (int kc = 0; kc < 4; kc++) {
                mma_bf16(sacc[nt], qa_h[kc], kbh + kc * 2);
                mma_bf16(sacc[nt], qa_l[kc], kbh + kc * 2);
                mma_bf16(sacc[nt], qa_h[kc], kbl + kc * 2);
            }
        }

        if (k0 + 31 > r0g) {
            const int cb = k0 + 2 * (lane & 3);
#pragma unroll
            for (int nt = 0; nt < 4; nt++) {
                int cc = cb + nt * 8;
                if (cc     > r0g)     sacc[nt][0] = -1e30f;
                if (cc + 1 > r0g)     sacc[nt][1] = -1e30f;
                if (cc     > r0g + 8) sacc[nt][2] = -1e30f;
                if (cc + 1 > r0g + 8) sacc[nt][3] = -1e30f;
            }
        }

        float mx0 = -1e30f, mx1 = -1e30f;
#pragma unroll
        for (int nt = 0; nt < 4; nt++) {
            mx0 = fmaxf(mx0, fmaxf(sacc[nt][0], sacc[nt][1]));
            mx1 = fmaxf(mx1, fmaxf(sacc[nt][2], sacc[nt][3]));
        }
        mx0 = fmaxf(mx0, __shfl_xor_sync(0xffffffffu, mx0, 1));
        mx0 = fmaxf(mx0, __shfl_xor_sync(0xffffffffu, mx0, 2));
        mx1 = fmaxf(mx1, __shfl_xor_sync(0xffffffffu, mx1, 1));
        mx1 = fmaxf(mx1, __shfl_xor_sync(0xffffffffu, mx1, 2));

        const float m0n = fmaxf(m0, mx0);
        const float m1n = fmaxf(m1, mx1);
        const float a0 = __expf(m0 - m0n);
        const float a1 = __expf(m1 - m1n);

        float rs0 = 0.f, rs1 = 0.f;
#pragma unroll
        for (int nt = 0; nt < 4; nt++) {
            float p0 = __expf(sacc[nt][0] - m0n);
            float p1 = __expf(sacc[nt][1] - m0n);
            float p2 = __expf(sacc[nt][2] - m1n);
            float p3 = __expf(sacc[nt][3] - m1n);
            sacc[nt][0] = p0; sacc[nt][1] = p1; sacc[nt][2] = p2; sacc[nt][3] = p3;
            rs0 += p0 + p1;
            rs1 += p2 + p3;
        }
        rs0 += __shfl_xor_sync(0xffffffffu, rs0, 1);
        rs0 += __shfl_xor_sync(0xffffffffu, rs0, 2);
        rs1 += __shfl_xor_sync(0xffffffffu, rs1, 1);
        rs1 += __shfl_xor_sync(0xffffffffu, rs1, 2);

        l0 = l0 * a0 + rs0;
        l1 = l1 * a1 + rs1;
        m0 = m0n;
        m1 = m1n;
#pragma unroll
        for (int nt = 0; nt < 8; nt++) {
            oacc[nt][0] *= a0; oacc[nt][1] *= a0;
            oacc[nt][2] *= a1; oacc[nt][3] *= a1;
        }

        uint32_t pa_h[2][4], pa_l[2][4];
#pragma unroll
        for (int kc = 0; kc < 2; kc++) {
#pragma unroll
            for (int half = 0; half < 2; half++) {
                const float* v = sacc[2 * kc + half];
                float h00 = __bfloat162float(__float2bfloat16(v[0]));
                float h01 = __bfloat162float(__float2bfloat16(v[1]));
                float h10 = __bfloat162float(__float2bfloat16(v[2]));
                float h11 = __bfloat162float(__float2bfloat16(v[3]));
                pa_h[kc][0 + 2 * half] = pack_bf16(h00, h01);
                pa_h[kc][1 + 2 * half] = pack_bf16(h10, h11);
                pa_l[kc][0 + 2 * half] = pack_bf16(v[0] - h00, v[1] - h01);
                pa_l[kc][1 + 2 * half] = pack_bf16(v[2] - h10, v[3] - h11);
            }
        }

#pragma unroll
        for (int np = 0; np < 4; np++) {
#pragma unroll
            for (int kc = 0; kc < 2; kc++) {
                uint32_t vbh[4], vbl[4];
                int g = lane >> 3;
                int key = kc * 16 + (g & 1) * 8 + (lane & 7);
                int dim = np * 16 + (g >> 1) * 8;
                uint32_t ad = (uint32_t)((key * FSTR + dim) * 2);
                ldsm_x4_t(vbh, aVh + ad);
                ldsm_x4_t(vbl, aVl + ad);
                mma_bf16(oacc[2 * np],     pa_h[kc], vbh);
                mma_bf16(oacc[2 * np],     pa_l[kc], vbh);
                mma_bf16(oacc[2 * np],     pa_h[kc], vbl);
                mma_bf16(oacc[2 * np + 1], pa_h[kc], vbh + 2);
                mma_bf16(oacc[2 * np + 1], pa_l[kc], vbh + 2);
                mma_bf16(oacc[2 * np + 1], pa_h[kc], vbl + 2);
            }
        }
        __syncthreads();
    }

    const float i0 = 1.f / l0;
    const float i1 = 1.f / l1;
    const size_t ob0 = ((size_t)b * Sq + r0g) * Dq + h * DKq + 2 * (lane & 3);
#pragma unroll
    for (int nt = 0; nt < 8; nt++) {
        float x0 = oacc[nt][0] * i0, x1 = oacc[nt][1] * i0;
        float y0 = oacc[nt][2] * i1, y1 = oacc[nt][3] * i1;
        float hx0 = __bfloat162float(__float2bfloat16(x0));
        float hx1 = __bfloat162float(__float2bfloat16(x1));
        float hy0 = __bfloat162float(__float2bfloat16(y0));
        float hy1 = __bfloat162float(__float2bfloat16(y1));
        size_t o0 = ob0 + nt * 8;
        size_t o1 = o0 + 8 * (size_t)Dq;
        *(uint32_t*)(AOh + o0) = pack_bf16(hx0, hx1);
        *(uint32_t*)(AOl + o0) = pack_bf16(x0 - hx0, x1 - hx1);
        *(uint32_t*)(AOh + o1) = pack_bf16(hy0, hy1);
        *(uint32_t*)(AOl + o1) = pack_bf16(y0 - hy0, y1 - hy1);
    }
}

// ---------------------------------------------------------------------------
extern "C" void kernel_launch(void* const* d_in, const int* in_sizes, int n_in,
                              void* d_out, int out_size)
{
    const float* x    = (const float*)d_in[0];
    const float* W_Q  = (const float*)d_in[1];
    const float* W_K  = (const float*)d_in[2];
    const float* W_V  = (const float*)d_in[3];
    const float* W_O  = (const float*)d_in[4];
    const float* gain = (const float*)d_in[5];
    float* out = (float*)d_out;

    float *Qp, *Kp, *sinp, *cosp;
    __nv_bfloat16 *xh, *xl, *aoh, *aol, *Wh, *Wl;
    __nv_bfloat16 *qh, *ql, *kh, *kl, *vh, *vl;
    cudaGetSymbolAddress((void**)&Qp,   g_Q);
    cudaGetSymbolAddress((void**)&Kp,   g_K);
    cudaGetSymbolAddress((void**)&sinp, g_sin);
    cudaGetSymbolAddress((void**)&cosp, g_cos);
    cudaGetSymbolAddress((void**)&xh,   g_xh);
    cudaGetSymbolAddress((void**)&xl,   g_xl);
    cudaGetSymbolAddress((void**)&aoh,  g_aoh);
    cudaGetSymbolAddress((void**)&aol,  g_aol);
    cudaGetSymbolAddress((void**)&Wh,   g_Wh);
    cudaGetSymbolAddress((void**)&Wl,   g_Wl);
    cudaGetSymbolAddress((void**)&qh,   g_Qh);
    cudaGetSymbolAddress((void**)&ql,   g_Ql);
    cudaGetSymbolAddress((void**)&kh,   g_Kh);
    cudaGetSymbolAddress((void**)&kl,   g_Kl);
    cudaGetSymbolAddress((void**)&vh,   g_Vh);
    cudaGetSymbolAddress((void**)&vl,   g_Vl);

    cudaFuncSetAttribute(gemm_tc,
                         cudaFuncAttributeMaxDynamicSharedMemorySize, GEMM_SMEM);
    cudaFuncSetAttribute(gemm_qkv,
                         cudaFuncAttributeMaxDynamicSharedMemorySize, GEMM_SMEM);
    cudaFuncSetAttribute(flash_tc,
                         cudaFuncAttributeMaxDynamicSharedMemorySize, FLASH_SMEM);

    const int nx4 = NR * Dq / 4;
    const int nw4 = Dq * Dq / 4;
    const size_t WSZ = (size_t)Dq * Dq;

    // splits + table
    split_kernel<<<nx4 / 256, 256>>>(x, xh, xl, nx4, 1.f);
    split_kernel<<<nw4 / 256, 256>>>(W_Q, Wh + 0*WSZ, Wl + 0*WSZ, nw4, 1.f);
    split_kernel<<<nw4 / 256, 256>>>(W_K, Wh + 1*WSZ, Wl + 1*WSZ, nw4, 1.f);
    split_kernel<<<nw4 / 256, 256>>>(W_V, Wh + 2*WSZ, Wl + 2*WSZ, nw4, 1.f);
    split_kernel<<<nw4 / 256, 256>>>(W_O, Wh + 3*WSZ, Wl + 3*WSZ, nw4, 1.f);
    rope_table_kernel<<<Sq * 32 / 256, 256>>>(sinp, cosp);

    // fused QKV projection (768 CTAs, better SM fill)
    gemm_qkv<<<dim3(3 * Dq / 128, NR / 128), 256, GEMM_SMEM>>>(
        xh, xl, Wh, Wl, Qp, Kp, vh, vl);

    // fused norm+rope+split (1/8 folded into Q)
    norm_rope_split<<<NR, 256>>>(Qp, qh, ql, gain, sinp, cosp, 0.125f);
    norm_rope_split<<<NR, 256>>>(Kp, kh, kl, gain, sinp, cosp, 1.f);

    // tensor-core flash attention (heaviest-first tile order)
    flash_tc<<<dim3(Sq / 64, Hq, Bq), 128, FLASH_SMEM>>>(qh, ql, kh, kl, vh, vl, aoh, aol);

    // output projection
    gemm_tc<<<dim3(Dq / 128, NR / 128), 256, GEMM_SMEM>>>(
        aoh, aol, Wh + 3*WSZ, Wl + 3*WSZ, out, NR, Dq, Dq);
}

// round 16
// speedup vs baseline: 1.6338x; 1.0325x over previous
#include <cuda_runtime.h>
#include <cuda_bf16.h>
#include <math.h>
#include <stdint.h>

// Problem constants (fixed by dataset)
#define Bq   2
#define Sq   2048
#define Dq   1024
#define Hq   16
#define DKq  64
#define NR   (Bq*Sq)          // 4096 token rows

// ---------------------------------------------------------------------------
// Scratch (allocation-free rule: __device__ globals)
// ---------------------------------------------------------------------------
__device__ float g_Q [NR*Dq];
__device__ float g_K [NR*Dq];
__device__ __nv_bfloat16 g_xh [NR*Dq];
__device__ __nv_bfloat16 g_xl [NR*Dq];
__device__ __nv_bfloat16 g_aoh[NR*Dq];
__device__ __nv_bfloat16 g_aol[NR*Dq];
__device__ __nv_bfloat16 g_Qh [NR*Dq];
__device__ __nv_bfloat16 g_Ql [NR*Dq];
__device__ __nv_bfloat16 g_Kh [NR*Dq];
__device__ __nv_bfloat16 g_Kl [NR*Dq];
__device__ __nv_bfloat16 g_Vh [NR*Dq];
__device__ __nv_bfloat16 g_Vl [NR*Dq];
__device__ __nv_bfloat16 g_Wh [4*Dq*Dq];   // WQ,WK,WV,WO hi
__device__ __nv_bfloat16 g_Wl [4*Dq*Dq];   // lo
__device__ float g_sin[Sq*32];
__device__ float g_cos[Sq*32];

#define LOG2E 1.4426950408889634f

// ---------------------------------------------------------------------------
// PTX helpers
// ---------------------------------------------------------------------------
__device__ __forceinline__ void mma_bf16(float* d, const uint32_t* a, const uint32_t* b) {
    asm volatile(
        "mma.sync.aligned.m16n8k16.row.col.f32.bf16.bf16.f32 "
        "{%0,%1,%2,%3}, {%4,%5,%6,%7}, {%8,%9}, {%0,%1,%2,%3};\n"
        : "+f"(d[0]), "+f"(d[1]), "+f"(d[2]), "+f"(d[3])
        : "r"(a[0]), "r"(a[1]), "r"(a[2]), "r"(a[3]), "r"(b[0]), "r"(b[1]));
}

__device__ __forceinline__ void ldsm_x4(uint32_t* r, uint32_t addr) {
    asm volatile("ldmatrix.sync.aligned.m8n8.x4.shared.b16 {%0,%1,%2,%3}, [%4];"
        : "=r"(r[0]), "=r"(r[1]), "=r"(r[2]), "=r"(r[3]) : "r"(addr));
}
__device__ __forceinline__ void ldsm_x4_t(uint32_t* r, uint32_t addr) {
    asm volatile("ldmatrix.sync.aligned.m8n8.x4.trans.shared.b16 {%0,%1,%2,%3}, [%4];"
        : "=r"(r[0]), "=r"(r[1]), "=r"(r[2]), "=r"(r[3]) : "r"(addr));
}
__device__ __forceinline__ void ldsm_x2(uint32_t* r, uint32_t addr) {
    asm volatile("ldmatrix.sync.aligned.m8n8.x2.shared.b16 {%0,%1}, [%2];"
        : "=r"(r[0]), "=r"(r[1]) : "r"(addr));
}

__device__ __forceinline__ uint32_t smem_u32(const void* p) {
    uint32_t a;
    asm("{ .reg .u64 t; cvta.to.shared.u64 t, %1; cvt.u32.u64 %0, t; }"
        : "=r"(a) : "l"(p));
    return a;
}

__device__ __forceinline__ uint32_t pack_bf16(float a, float b) {
    __nv_bfloat162 t = __floats2bfloat162_rn(a, b);
    return *reinterpret_cast<uint32_t*>(&t);
}

__device__ __forceinline__ float ex2f(float x) {
    float r;
    asm("ex2.approx.f32 %0, %1;" : "=f"(r) : "f"(x));
    return r;
}

__device__ __forceinline__ void cp16(uint32_t saddr, const void* gaddr) {
    asm volatile("cp.async.cg.shared.global [%0], [%1], 16;"
        :: "r"(saddr), "l"(gaddr));
}
#define CP_COMMIT() asm volatile("cp.async.commit_group;")
#define CP_WAIT1()  asm volatile("cp.async.wait_group 1;")
#define CP_WAIT0()  asm volatile("cp.async.wait_group 0;")

// ---------------------------------------------------------------------------
// Mega-split: x + 4 weight matrices -> bf16 hi/lo in ONE launch.
// Segments: [0, NX) = x ; [NX, NX+4*NW) = W_Q,W_K,W_V,W_O.
// ---------------------------------------------------------------------------
#define NX4 (NR * Dq / 4)         // 1M float4
#define NW4 (Dq * Dq / 4)         // 256K float4

__global__ void __launch_bounds__(256) split_all(const float* __restrict__ x,
                                                 const float* __restrict__ wq,
                                                 const float* __restrict__ wk,
                                                 const float* __restrict__ wv,
                                                 const float* __restrict__ wo,
                                                 __nv_bfloat16* __restrict__ xh,
                                                 __nv_bfloat16* __restrict__ xl,
                                                 __nv_bfloat16* __restrict__ Wh,
                                                 __nv_bfloat16* __restrict__ Wl)
{
    int i = blockIdx.x * 256 + threadIdx.x;   // 0 .. NX4+4*NW4-1
    const float* src;
    __nv_bfloat16 *H, *L;
    int off;
    if (i < NX4) {
        src = x; off = i; H = xh; L = xl;
    } else {
        int j = i - NX4;
        int w = j / NW4;
        off = j - w * NW4;
        src = (w == 0) ? wq : (w == 1) ? wk : (w == 2) ? wv : wo;
        size_t wb = (size_t)w * (Dq * Dq);
        H = Wh + wb; L = Wl + wb;
    }
    float4 v = ((const float4*)src)[off];
    float f[4] = {v.x, v.y, v.z, v.w};
    __nv_bfloat16 h[4], l[4];
#pragma unroll
    for (int j = 0; j < 4; j++) {
        h[j] = __float2bfloat16(f[j]);
        l[j] = __float2bfloat16(f[j] - __bfloat162float(h[j]));
    }
    uint32_t* H32 = (uint32_t*)H;
    uint32_t* L32 = (uint32_t*)L;
    H32[2*off]   = pack_bf16(__bfloat162float(h[0]), __bfloat162float(h[1]));
    H32[2*off+1] = pack_bf16(__bfloat162float(h[2]), __bfloat162float(h[3]));
    L32[2*off]   = pack_bf16(__bfloat162float(l[0]), __bfloat162float(l[1]));
    L32[2*off+1] = pack_bf16(__bfloat162float(l[2]), __bfloat162float(l[3]));
}

// ---------------------------------------------------------------------------
// GEMM mainloop core (2-stage cp.async, K-chunk 32) shared by both kernels.
// ---------------------------------------------------------------------------
#define GS2   40
#define GT2   (128 * GS2)
#define GSTG  (4 * GT2 * 2)
#define GEMM_SMEM (2 * GSTG)

struct GemmAcc { float a[4][4][4]; };

__device__ __forceinline__ void gemm_mainloop(
    const __nv_bfloat16* __restrict__ Ah, const __nv_bfloat16* __restrict__ Al,
    const __nv_bfloat16* __restrict__ Bh, const __nv_bfloat16* __restrict__ Bl,
    int bm, int bn, int K, uint32_t sb, int tid, GemmAcc& acc)
{
    const int lane = tid & 31;
    const int wid  = tid >> 5;
    const int wm   = (wid >> 2) * 64;
    const int wn   = (wid & 3) * 32;

#pragma unroll
    for (int mt = 0; mt < 4; mt++)
#pragma unroll
        for (int nt = 0; nt < 4; nt++)
#pragma unroll
            for (int r = 0; r < 4; r++) acc.a[mt][nt][r] = 0.f;

    const uint32_t offA = ((lane & 15) * GS2 + (lane >> 4) * 8) * 2;
    const uint32_t offB = ((lane & 7) * GS2 + ((lane >> 3) & 1) * 8) * 2;

    auto issue = [&](int kt, int s) {
        const int k0 = kt * 32;
        const uint32_t stb = sb + s * GSTG;
#pragma unroll
        for (int j = 0; j < 2; j++) {
            int idx = tid + j * 256;
            int row = idx >> 2;
            int cq  = idx & 3;
            uint32_t so = (uint32_t)(row * GS2 + cq * 8) * 2;
            size_t ga = (size_t)(bm + row) * K + k0 + cq * 8;
            size_t gb = (size_t)(bn + row) * K + k0 + cq * 8;
            cp16(stb               + so, Ah + ga);
            cp16(stb + GT2 * 2     + so, Al + ga);
            cp16(stb + 2 * GT2 * 2 + so, Bh + gb);
            cp16(stb + 3 * GT2 * 2 + so, Bl + gb);
        }
        CP_COMMIT();
    };

    const int KT = K / 32;
    issue(0, 0);

    for (int kt = 0; kt < KT; kt++) {
        if (kt + 1 < KT) {
            issue(kt + 1, (kt + 1) & 1);
            CP_WAIT1();
        } else {
            CP_WAIT0();
        }
        __syncthreads();

        const uint32_t stb = sb + (kt & 1) * GSTG;
        const uint32_t aAh = stb;
        const uint32_t aAl = stb + GT2 * 2;
        const uint32_t aBh = stb + 2 * GT2 * 2;
        const uint32_t aBl = stb + 3 * GT2 * 2;

#pragma unroll
        for (int ks = 0; ks < 2; ks++) {
            const uint32_t kof = (uint32_t)(ks * 16 * 2);
            uint32_t bh[4][2], bl[4][2], af[4][4];
#pragma unroll
            for (int nt = 0; nt < 4; nt++) {
                uint32_t ro = (uint32_t)((wn + nt * 8) * GS2 * 2) + kof;
                ldsm_x2(bh[nt], aBh + ro + offB);
                ldsm_x2(bl[nt], aBl + ro + offB);
            }
#pragma unroll
            for (int mt = 0; mt < 4; mt++) {
                uint32_t ro = (uint32_t)((wm + mt * 16) * GS2 * 2) + kof;
                ldsm_x4(af[mt], aAh + ro + offA);
            }
#pragma unroll
            for (int mt = 0; mt < 4; mt++)
#pragma unroll
                for (int nt = 0; nt < 4; nt++) {
                    mma_bf16(acc.a[mt][nt], af[mt], bh[nt]);
                    mma_bf16(acc.a[mt][nt], af[mt], bl[nt]);
                }
#pragma unroll
            for (int mt = 0; mt < 4; mt++) {
                uint32_t ro = (uint32_t)((wm + mt * 16) * GS2 * 2) + kof;
                ldsm_x4(af[mt], aAl + ro + offA);
            }
#pragma unroll
            for (int mt = 0; mt < 4; mt++)
#pragma unroll
                for (int nt = 0; nt < 4; nt++)
                    mma_bf16(acc.a[mt][nt], af[mt], bh[nt]);
        }
        __syncthreads();
    }
}

// fp32-epilogue GEMM (WO output projection)
__global__ void __launch_bounds__(256) gemm_tc(const __nv_bfloat16* __restrict__ Ah,
                                               const __nv_bfloat16* __restrict__ Al,
                                               const __nv_bfloat16* __restrict__ Bh,
                                               const __nv_bfloat16* __restrict__ Bl,
                                               float* __restrict__ C,
                                               int M, int N, int K)
{
    extern __shared__ __nv_bfloat16 smg[];
    const int tid = threadIdx.x;
    const int bm  = blockIdx.y * 128;
    const int bn  = blockIdx.x * 128;
    GemmAcc acc;
    gemm_mainloop(Ah, Al, Bh, Bl, bm, bn, K, smem_u32(smg), tid, acc);

    const int lane = tid & 31;
    const int wid  = tid >> 5;
    const int wm   = (wid >> 2) * 64;
    const int wn   = (wid & 3) * 32;
    const int er = lane >> 2;
    const int ec = (lane & 3) * 2;
#pragma unroll
    for (int mt = 0; mt < 4; mt++) {
        const int row = bm + wm + mt * 16 + er;
#pragma unroll
        for (int nt = 0; nt < 4; nt++) {
            const int col = bn + wn + nt * 8 + ec;
            *(float2*)(C + (size_t)row * N + col) =
                make_float2(acc.a[mt][nt][0], acc.a[mt][nt][1]);
            *(float2*)(C + (size_t)(row + 8) * N + col) =
                make_float2(acc.a[mt][nt][2], acc.a[mt][nt][3]);
        }
    }
}

// Fused QKV projection: per-CTA W select. w=0 Q fp32, w=1 K fp32, w=2 V hi/lo.
__global__ void __launch_bounds__(256) gemm_qkv(const __nv_bfloat16* __restrict__ Ah,
                                                const __nv_bfloat16* __restrict__ Al,
                                                const __nv_bfloat16* __restrict__ Wh,
                                                const __nv_bfloat16* __restrict__ Wl,
                                                float* __restrict__ Qp,
                                                float* __restrict__ Kp,
                                                __nv_bfloat16* __restrict__ Vh,
                                                __nv_bfloat16* __restrict__ Vl)
{
    extern __shared__ __nv_bfloat16 smg[];
    const int tid = threadIdx.x;
    const int bm  = blockIdx.y * 128;
    const int bng = blockIdx.x * 128;
    const int w   = bng >> 10;
    const int bn  = bng & 1023;
    const size_t WSZ = (size_t)Dq * Dq;

    GemmAcc acc;
    gemm_mainloop(Ah, Al, Wh + (size_t)w * WSZ, Wl + (size_t)w * WSZ,
                  bm, bn, Dq, smem_u32(smg), tid, acc);

    const int lane = tid & 31;
    const int wid  = tid >> 5;
    const int wm   = (wid >> 2) * 64;
    const int wn   = (wid & 3) * 32;
    const int er = lane >> 2;
    const int ec = (lane & 3) * 2;

    if (w < 2) {
        float* C = (w == 0) ? Qp : Kp;
#pragma unroll
        for (int mt = 0; mt < 4; mt++) {
            const int row = bm + wm + mt * 16 + er;
#pragma unroll
            for (int nt = 0; nt < 4; nt++) {
                const int col = bn + wn + nt * 8 + ec;
                *(float2*)(C + (size_t)row * Dq + col) =
                    make_float2(acc.a[mt][nt][0], acc.a[mt][nt][1]);
                *(float2*)(C + (size_t)(row + 8) * Dq + col) =
                    make_float2(acc.a[mt][nt][2], acc.a[mt][nt][3]);
            }
        }
    } else {
#pragma unroll
        for (int mt = 0; mt < 4; mt++) {
            const int row = bm + wm + mt * 16 + er;
#pragma unroll
            for (int nt = 0; nt < 4; nt++) {
                const int col = bn + wn + nt * 8 + ec;
                float v0 = acc.a[mt][nt][0], v1 = acc.a[mt][nt][1];
                float v2 = acc.a[mt][nt][2], v3 = acc.a[mt][nt][3];
                float h0 = __bfloat162float(__float2bfloat16(v0));
                float h1 = __bfloat162float(__float2bfloat16(v1));
                float h2 = __bfloat162float(__float2bfloat16(v2));
                float h3 = __bfloat162float(__float2bfloat16(v3));
                *(uint32_t*)(Vh + (size_t)row * Dq + col)       = pack_bf16(h0, h1);
                *(uint32_t*)(Vl + (size_t)row * Dq + col)       = pack_bf16(v0 - h0, v1 - h1);
                *(uint32_t*)(Vh + (size_t)(row + 8) * Dq + col) = pack_bf16(h2, h3);
                *(uint32_t*)(Vl + (size_t)(row + 8) * Dq + col) = pack_bf16(v2 - h2, v3 - h3);
            }
        }
    }
}

// ---------------------------------------------------------------------------
// RoPE table: sin/cos[s][p] for s<2048, p<32.
// ---------------------------------------------------------------------------
__global__ void __launch_bounds__(256) rope_table_kernel(float* __restrict__ st,
                                                         float* __restrict__ ct)
{
    int i = blockIdx.x * 256 + threadIdx.x;
    int s = i >> 5, p = i & 31;
    double f = exp(-(double)p * (9.210340371976184 / 32.0));
    float a = (float)((double)s * f);
    float sv, cv;
    sincosf(a, &sv, &cv);
    st[i] = sv;
    ct[i] = cv;
}

// ---------------------------------------------------------------------------
// Merged RMSNorm + RoPE + hi/lo split for Q AND K in one launch.
// blockIdx.x < NR -> Q (scale 0.125*log2e), else K (scale 1).
// ---------------------------------------------------------------------------
__global__ void __launch_bounds__(256) norm_rope_split2(const float* __restrict__ Qf,
                                                        const float* __restrict__ Kf,
                                                        __nv_bfloat16* __restrict__ QH,
                                                        __nv_bfloat16* __restrict__ QL,
                                                        __nv_bfloat16* __restrict__ KH,
                                                        __nv_bfloat16* __restrict__ KL,
                                                        const float* __restrict__ gain,
                                                        const float* __restrict__ st,
                                                        const float* __restrict__ ct)
{
    const bool isQ = blockIdx.x < NR;
    const int n = isQ ? blockIdx.x : (blockIdx.x - NR);
    const float scale = isQ ? (0.125f * LOG2E) : 1.f;
    const float* row = (isQ ? Qf : Kf) + (size_t)n * Dq;
    __nv_bfloat16* H = (isQ ? QH : KH);
    __nv_bfloat16* L = (isQ ? QL : KL);
    const int s = n % Sq;
    const int t = threadIdx.x;

    float4 x = ((const float4*)row)[t];
    float ss = x.x * x.x + x.y * x.y + x.z * x.z + x.w * x.w;
#pragma unroll
    for (int o = 16; o > 0; o >>= 1) ss += __shfl_xor_sync(0xffffffffu, ss, o);

    __shared__ float wsum[8];
    if ((t & 31) == 0) wsum[t >> 5] = ss;
    __syncthreads();
    float tot = 0.f;
#pragma unroll
    for (int i = 0; i < 8; i++) tot += wsum[i];

    const float rinv = rsqrtf(tot * (1.0f / 1024.0f) + 1e-5f);
    const float4 g = ((const float4*)gain)[t];

    const int p0 = ((t * 4) & 63) >> 1;
    const float s0 = st[s * 32 + p0],     c0 = ct[s * 32 + p0];
    const float s1 = st[s * 32 + p0 + 1], c1 = ct[s * 32 + p0 + 1];

    const float e0 = x.x * rinv * g.x, o0 = x.y * rinv * g.y;
    const float e1 = x.z * rinv * g.z, o1 = x.w * rinv * g.w;

    float r0 = (e0 * c0 - o0 * s0) * scale;
    float r1 = (o0 * c0 + e0 * s0) * scale;
    float r2 = (e1 * c1 - o1 * s1) * scale;
    float r3 = (o1 * c1 + e1 * s1) * scale;

    float h0 = __bfloat162float(__float2bfloat16(r0));
    float h1 = __bfloat162float(__float2bfloat16(r1));
    float h2 = __bfloat162float(__float2bfloat16(r2));
    float h3 = __bfloat162float(__float2bfloat16(r3));

    uint32_t* H32 = (uint32_t*)(H + (size_t)n * Dq);
    uint32_t* L32 = (uint32_t*)(L + (size_t)n * Dq);
    H32[2*t]   = pack_bf16(h0, h1);
    H32[2*t+1] = pack_bf16(h2, h3);
    L32[2*t]   = pack_bf16(r0 - h0, r1 - h1);
    L32[2*t+1] = pack_bf16(r2 - h2, r3 - h3);
}

// ---------------------------------------------------------------------------
// Tensor-core causal flash attention (R14 winner) + exp2-domain softmax
// with deferred l-reduction. Scores arrive pre-scaled by 0.125*log2e.
// ---------------------------------------------------------------------------
#define FSTR 72
#define FQ   (64 * FSTR)
#define FK   (32 * FSTR)
#define FSTG_B (4 * FK * 2)
#define FLASH_SMEM (2 * FQ * 2 + 2 * FSTG_B)   // 55,296 B

__global__ void __launch_bounds__(128) flash_tc(
    const __nv_bfloat16* __restrict__ Qh, const __nv_bfloat16* __restrict__ Ql,
    const __nv_bfloat16* __restrict__ Kh, const __nv_bfloat16* __restrict__ Kl,
    const __nv_bfloat16* __restrict__ Vh, const __nv_bfloat16* __restrict__ Vl,
    __nv_bfloat16* __restrict__ AOh, __nv_bfloat16* __restrict__ AOl)
{
    extern __shared__ __nv_bfloat16 smf[];

    const int tid  = threadIdx.x;
    const int lane = tid & 31;
    const int warp = tid >> 5;
    const int qtile = (int)gridDim.x - 1 - (int)blockIdx.x;   // heaviest first
    const int q0 = qtile * 64;
    const int h  = blockIdx.y;
    const int b  = blockIdx.z;

    const uint32_t sb   = smem_u32(smf);
    const uint32_t aQh  = sb;
    const uint32_t aQl  = sb + FQ * 2;
    const uint32_t kvsb = sb + 2 * FQ * 2;

    const size_t kvbase = ((size_t)b * Sq) * Dq + h * DKq;

    auto issue_kv = [&](int c, int s) {
        const int k0 = c * 32;
        const uint32_t stb = kvsb + s * FSTG_B;
#pragma unroll
        for (int j = 0; j < 8; j++) {
            int idx = tid + j * 128;
            int tile = idx >> 8;
            int row  = (idx >> 3) & 31;
            int cq   = idx & 7;
            uint32_t so = stb + (uint32_t)(tile * FK * 2) +
                          (uint32_t)(row * FSTR + cq * 8) * 2;
            size_t g = kvbase + (size_t)(k0 + row) * Dq + cq * 8;
            const __nv_bfloat16* src =
                (tile == 0) ? (Kh + g) : (tile == 1) ? (Kl + g)
              : (tile == 2) ? (Vh + g) : (Vl + g);
            cp16(so, src);
        }
        CP_COMMIT();
    };

    issue_kv(0, 0);

    {
        const size_t gbase = ((size_t)b * Sq + q0) * Dq + h * DKq;
        __nv_bfloat16* sQh = smf;
        __nv_bfloat16* sQl = smf + FQ;
#pragma unroll
        for (int j = 0; j < 4; j++) {
            int idx = tid + j * 128;
            int row = idx >> 3;
            int cq  = idx & 7;
            size_t g = gbase + (size_t)row * Dq + cq * 8;
            uint32_t so = (uint32_t)(row * FSTR + cq * 8);
            *(uint4*)(sQh + so) = *(const uint4*)(Qh + g);
            *(uint4*)(sQl + so) = *(const uint4*)(Ql + g);
        }
    }
    __syncthreads();

    uint32_t qa_h[4][4], qa_l[4][4];
    const uint32_t offA = (uint32_t)(((lane & 15) * FSTR + (lane >> 4) * 8) * 2);
    const uint32_t qwb  = (uint32_t)(warp * 16 * FSTR * 2);
#pragma unroll
    for (int kc = 0; kc < 4; kc++) {
        ldsm_x4(qa_h[kc], aQh + qwb + (uint32_t)(kc * 32) + offA);
        ldsm_x4(qa_l[kc], aQl + qwb + (uint32_t)(kc * 32) + offA);
    }

    float m0 = -1e30f, m1 = -1e30f, l0p = 0.f, l1p = 0.f;   // l: per-lane partials
    float oacc[8][4];
#pragma unroll
    for (int nt = 0; nt < 8; nt++)
#pragma unroll
        for (int r = 0; r < 4; r++) oacc[nt][r] = 0.f;

    const int r0g = q0 + warp * 16 + (lane >> 2);

    const int nchunks = 2 * (qtile + 1);
    for (int c = 0; c < nchunks; c++) {
        const int k0 = c * 32;
        if (c + 1 < nchunks) {
            issue_kv(c + 1, (c + 1) & 1);
            CP_WAIT1();
        } else {
            CP_WAIT0();
        }
        __syncthreads();

        const uint32_t stb = kvsb + (c & 1) * FSTG_B;
        const uint32_t aKh = stb;
        const uint32_t aKl = stb + FK * 2;
        const uint32_t aVh = stb + 2 * FK * 2;
        const uint32_t aVl = stb + 3 * FK * 2;

        float sacc[4][4];
#pragma unroll
        for (int nt = 0; nt < 4; nt++)
#pragma unroll
            for (int r = 0; r < 4; r++) sacc[nt][r] = 0.f;

#pragma unroll
        for (int nt = 0; nt < 4; nt++) {
            uint32_t kbh[8], kbl[8];
            uint32_t rb = (uint32_t)(((nt * 8 + (lane & 7)) * FSTR + (lane >> 3) * 8) * 2);
            ldsm_x4(kbh,     aKh + rb);
            ldsm_x4(kbh + 4, aKh + rb + 64);
            ldsm_x4(kbl,     aKl + rb);
            ldsm_x4(kbl + 4, aKl + rb + 64);
#pragma unroll
            for (int kc = 0; kc < 4; kc++) {
                mma_bf16(sacc[nt], qa_h[kc], kbh + kc * 2);
                mma_bf16(sacc[nt], qa_l[kc], kbh + kc * 2);
                mma_bf16(sacc[nt], qa_h[kc], kbl + kc * 2);
            }
        }

        if (k0 + 31 > r0g) {
            const int cb = k0 + 2 * (lane & 3);
#pragma unroll
            for (int nt = 0; nt < 4; nt++) {
                int cc = cb + nt * 8;
                if (cc     > r0g)     sacc[nt][0] = -1e30f;
                if (cc + 1 > r0g)     sacc[nt][1] = -1e30f;
                if (cc     > r0g + 8) sacc[nt][2] = -1e30f;
                if (cc + 1 > r0g + 8) sacc[nt][3] = -1e30f;
            }
        }

        float mx0 = -1e30f, mx1 = -1e30f;
#pragma unroll
        for (int nt = 0; nt < 4; nt++) {
            mx0 = fmaxf(mx0, fmaxf(sacc[nt][0], sacc[nt][1]));
            mx1 = fmaxf(mx1, fmaxf(sacc[nt][2], sacc[nt][3]));
        }
        mx0 = fmaxf(mx0, __shfl_xor_sync(0xffffffffu, mx0, 1));
        mx0 = fmaxf(mx0, __shfl_xor_sync(0xffffffffu, mx0, 2));
        mx1 = fmaxf(mx1, __shfl_xor_sync(0xffffffffu, mx1, 1));
        mx1 = fmaxf(mx1, __shfl_xor_sync(0xffffffffu, mx1, 2));

        const float m0n = fmaxf(m0, mx0);
        const float m1n = fmaxf(m1, mx1);
        const float a0 = ex2f(m0 - m0n);
        const float a1 = ex2f(m1 - m1n);

        // per-lane partial row sums (quad-reduced once at the end)
        l0p *= a0;
        l1p *= a1;
#pragma unroll
        for (int nt = 0; nt < 4; nt++) {
            float p0 = ex2f(sacc[nt][0] - m0n);
            float p1 = ex2f(sacc[nt][1] - m0n);
            float p2 = ex2f(sacc[nt][2] - m1n);
            float p3 = ex2f(sacc[nt][3] - m1n);
            sacc[nt][0] = p0; sacc[nt][1] = p1; sacc[nt][2] = p2; sacc[nt][3] = p3;
            l0p += p0 + p1;
            l1p += p2 + p3;
        }

        m0 = m0n;
        m1 = m1n;
#pragma unroll
        for (int nt = 0; nt < 8; nt++) {
            oacc[nt][0] *= a0; oacc[nt][1] *= a0;
            oacc[nt][2] *= a1; oacc[nt][3] *= a1;
        }

        uint32_t pa_h[2][4], pa_l[2][4];
#pragma unroll
        for (int kc = 0; kc < 2; kc++) {
#pragma unroll
            for (int half = 0; half < 2; half++) {
                const float* v = sacc[2 * kc + half];
                float h00 = __bfloat162float(__float2bfloat16(v[0]));
                float h01 = __bfloat162float(__float2bfloat16(v[1]));
                float h10 = __bfloat162float(__float2bfloat16(v[2]));
                float h11 = __bfloat162float(__float2bfloat16(v[3]));
                pa_h[kc][0 + 2 * half] = pack_bf16(h00, h01);
                pa_h[kc][1 + 2 * half] = pack_bf16(h10, h11);
                pa_l[kc][0 + 2 * half] = pack_bf16(v[0] - h00, v[1] - h01);
                pa_l[kc][1 + 2 * half] = pack_bf16(v[2] - h10, v[3] - h11);
            }
        }

#pragma unroll
        for (int np = 0; np < 4; np++) {
#pragma unroll
            for (int kc = 0; kc < 2; kc++) {
                uint32_t vbh[4], vbl[4];
                int g = lane >> 3;
                int key = kc * 16 + (g & 1) * 8 + (lane & 7);
                int dim = np * 16 + (g >> 1) * 8;
                uint32_t ad = (uint32_t)((key * FSTR + dim) * 2);
                ldsm_x4_t(vbh, aVh + ad);
                ldsm_x4_t(vbl, aVl + ad);
                mma_bf16(oacc[2 * np],     pa_h[kc], vbh);
                mma_bf16(oacc[2 * np],     pa_l[kc], vbh);
                mma_bf16(oacc[2 * np],     pa_h[kc], vbl);
                mma_bf16(oacc[2 * np + 1], pa_h[kc], vbh + 2);
                mma_bf16(oacc[2 * np + 1], pa_l[kc], vbh + 2);
                mma_bf16(oacc[2 * np + 1], pa_h[kc], vbl + 2);
            }
        }
        __syncthreads();
    }

    // final quad reduction of l partials
    float l0 = l0p, l1 = l1p;
    l0 += __shfl_xor_sync(0xffffffffu, l0, 1);
    l0 += __shfl_xor_sync(0xffffffffu, l0, 2);
    l1 += __shfl_xor_sync(0xffffffffu, l1, 1);
    l1 += __shfl_xor_sync(0xffffffffu, l1, 2);

    const float i0 = 1.f / l0;
    const float i1 = 1.f / l1;
    const size_t ob0 = ((size_t)b * Sq + r0g) * Dq + h * DKq + 2 * (lane & 3);
#pragma unroll
    for (int nt = 0; nt < 8; nt++) {
        float x0 = oacc[nt][0] * i0, x1 = oacc[nt][1] * i0;
        float y0 = oacc[nt][2] * i1, y1 = oacc[nt][3] * i1;
        float hx0 = __bfloat162float(__float2bfloat16(x0));
        float hx1 = __bfloat162float(__float2bfloat16(x1));
        float hy0 = __bfloat162float(__float2bfloat16(y0));
        float hy1 = __bfloat162float(__float2bfloat16(y1));
        size_t o0 = ob0 + nt * 8;
        size_t o1 = o0 + 8 * (size_t)Dq;
        *(uint32_t*)(AOh + o0) = pack_bf16(hx0, hx1);
        *(uint32_t*)(AOl + o0) = pack_bf16(x0 - hx0, x1 - hx1);
        *(uint32_t*)(AOh + o1) = pack_bf16(hy0, hy1);
        *(uint32_t*)(AOl + o1) = pack_bf16(y0 - hy0, y1 - hy1);
    }
}

// ---------------------------------------------------------------------------
extern "C" void kernel_launch(void* const* d_in, const int* in_sizes, int n_in,
                              void* d_out, int out_size)
{
    const float* x    = (const float*)d_in[0];
    const float* W_Q  = (const float*)d_in[1];
    const float* W_K  = (const float*)d_in[2];
    const float* W_V  = (const float*)d_in[3];
    const float* W_O  = (const float*)d_in[4];
    const float* gain = (const float*)d_in[5];
    float* out = (float*)d_out;

    float *Qp, *Kp, *sinp, *cosp;
    __nv_bfloat16 *xh, *xl, *aoh, *aol, *Wh, *Wl;
    __nv_bfloat16 *qh, *ql, *kh, *kl, *vh, *vl;
    cudaGetSymbolAddress((void**)&Qp,   g_Q);
    cudaGetSymbolAddress((void**)&Kp,   g_K);
    cudaGetSymbolAddress((void**)&sinp, g_sin);
    cudaGetSymbolAddress((void**)&cosp, g_cos);
    cudaGetSymbolAddress((void**)&xh,   g_xh);
    cudaGetSymbolAddress((void**)&xl,   g_xl);
    cudaGetSymbolAddress((void**)&aoh,  g_aoh);
    cudaGetSymbolAddress((void**)&aol,  g_aol);
    cudaGetSymbolAddress((void**)&Wh,   g_Wh);
    cudaGetSymbolAddress((void**)&Wl,   g_Wl);
    cudaGetSymbolAddress((void**)&qh,   g_Qh);
    cudaGetSymbolAddress((void**)&ql,   g_Ql);
    cudaGetSymbolAddress((void**)&kh,   g_Kh);
    cudaGetSymbolAddress((void**)&kl,   g_Kl);
    cudaGetSymbolAddress((void**)&vh,   g_Vh);
    cudaGetSymbolAddress((void**)&vl,   g_Vl);

    cudaFuncSetAttribute(gemm_tc,
                         cudaFuncAttributeMaxDynamicSharedMemorySize, GEMM_SMEM);
    cudaFuncSetAttribute(gemm_qkv,
                         cudaFuncAttributeMaxDynamicSharedMemorySize, GEMM_SMEM);
    cudaFuncSetAttribute(flash_tc,
                         cudaFuncAttributeMaxDynamicSharedMemorySize, FLASH_SMEM);

    const size_t WSZ = (size_t)Dq * Dq;
    const int nsplit = NX4 + 4 * NW4;     // 2M float4

    // one mega-split + table
    split_all<<<nsplit / 256, 256>>>(x, W_Q, W_K, W_V, W_O, xh, xl, Wh, Wl);
    rope_table_kernel<<<Sq * 32 / 256, 256>>>(sinp, cosp);

    // fused QKV projection
    gemm_qkv<<<dim3(3 * Dq / 128, NR / 128), 256, GEMM_SMEM>>>(
        xh, xl, Wh, Wl, Qp, Kp, vh, vl);

    // merged norm+rope+split for Q and K (log2e*0.125 folded into Q)
    norm_rope_split2<<<2 * NR, 256>>>(Qp, Kp, qh, ql, kh, kl, gain, sinp, cosp);

    // tensor-core flash attention (exp2 softmax, heaviest-first)
    flash_tc<<<dim3(Sq / 64, Hq, Bq), 128, FLASH_SMEM>>>(qh, ql, kh, kl, vh, vl, aoh, aol);

    // output projection
    gemm_tc<<<dim3(Dq / 128, NR / 128), 256, GEMM_SMEM>>>(
        aoh, aol, Wh + 3*WSZ, Wl + 3*WSZ, out, NR, Dq, Dq);
}